// round 1
// baseline (speedup 1.0000x reference)
#include <cuda_runtime.h>
#include <math.h>

#define N_TOK 8192
#define F_DIM 256
#define OUTD  64
#define NSPLIT 4
#define JCHUNK (N_TOK / NSPLIT)   /* 2048 */
#define M_TILE 128
#define J_TILE 128
#define PS_STRIDE 132             /* padded: conflict-free Ps reads */
#define VS_STRIDE 68              /* padded float4-aligned */

/* scratch (no allocation allowed) */
__device__ float g_fts[N_TOK * OUTD];            /* 2 MB  */
__device__ float g_f1[N_TOK];
__device__ float g_f2[N_TOK];
__device__ float g_f2max;
__device__ float g_acc[NSPLIT * N_TOK * OUTD];   /* 8 MB  */
__device__ float g_den[NSPLIT * N_TOK];

__device__ __forceinline__ unsigned long long pack2(float lo, float hi) {
    unsigned long long r;
    asm("mov.b64 %0, {%1, %2};" : "=l"(r) : "f"(lo), "f"(hi));
    return r;
}
__device__ __forceinline__ void unpack2(unsigned long long v, float &lo, float &hi) {
    asm("mov.b64 {%0, %1}, %2;" : "=f"(lo), "=f"(hi) : "l"(v));
}
/* packed fp32x2 FMA (Blackwell FFMA2) */
__device__ __forceinline__ void fma2(unsigned long long &d, unsigned long long a, unsigned long long b) {
    asm("fma.rn.f32x2 %0, %1, %2, %0;" : "+l"(d) : "l"(a), "l"(b));
}

/* ------------------------------------------------------------------ */
/* k1: seq_fts = seq @ W1 ; f1 = fts@a1+b1 ; f2 = fts@a2+b2            */
/* grid 128 blocks x 256 thr. Block covers 64 rows x 64 cols, K=256.   */
/* Thread computes 4x4 register tile.                                  */
/* ------------------------------------------------------------------ */
__global__ __launch_bounds__(256) void k1_fts(const float* __restrict__ seq,
        const float* __restrict__ W1, const float* __restrict__ a1,
        const float* __restrict__ b1, const float* __restrict__ a2,
        const float* __restrict__ b2) {
    __shared__ float As[64 * 68];
    __shared__ float Bs[64 * 64];
    __shared__ float a1s[OUTD], a2s[OUTD];

    const int tid = threadIdx.x;
    const int rb  = blockIdx.x * 64;
    if (tid < OUTD) { a1s[tid] = a1[tid]; a2s[tid] = a2[tid]; }

    const int cg = tid & 15, rg = tid >> 4;
    const int r0 = rg * 4,  c0 = cg * 4;

    float acc[4][4];
#pragma unroll
    for (int i = 0; i < 4; ++i)
#pragma unroll
        for (int j = 0; j < 4; ++j) acc[i][j] = 0.f;

    const float4* seq4 = (const float4*)seq;
    const float4* W14  = (const float4*)W1;
    float4* As4 = (float4*)As;   /* row stride 17 float4 */
    float4* Bs4 = (float4*)Bs;   /* row stride 16 float4 */

    for (int kb = 0; kb < 4; ++kb) {
        __syncthreads();
#pragma unroll
        for (int t = tid; t < 1024; t += 256) {
            const int r = t >> 4, c4 = t & 15;
            As4[r * 17 + c4] = seq4[(rb + r) * 64 + kb * 16 + c4];
            Bs4[t]           = W14[(kb * 64 + r) * 16 + c4];
        }
        __syncthreads();
#pragma unroll
        for (int k = 0; k < 64; ++k) {
            const float4 b = Bs4[k * 16 + cg];
#pragma unroll
            for (int ri = 0; ri < 4; ++ri) {
                const float a = As[(r0 + ri) * 68 + k];
                acc[ri][0] += a * b.x; acc[ri][1] += a * b.y;
                acc[ri][2] += a * b.z; acc[ri][3] += a * b.w;
            }
        }
    }

    float4* fts4 = (float4*)g_fts;
#pragma unroll
    for (int ri = 0; ri < 4; ++ri) {
        float4 v = make_float4(acc[ri][0], acc[ri][1], acc[ri][2], acc[ri][3]);
        fts4[(rb + r0 + ri) * 16 + cg] = v;
        float p1 = v.x * a1s[c0] + v.y * a1s[c0 + 1] + v.z * a1s[c0 + 2] + v.w * a1s[c0 + 3];
        float p2 = v.x * a2s[c0] + v.y * a2s[c0 + 1] + v.z * a2s[c0 + 2] + v.w * a2s[c0 + 3];
#pragma unroll
        for (int off = 8; off > 0; off >>= 1) {
            p1 += __shfl_xor_sync(0xffffffffu, p1, off);
            p2 += __shfl_xor_sync(0xffffffffu, p2, off);
        }
        if (cg == 0) {
            g_f1[rb + r0 + ri] = p1 + b1[0];
            g_f2[rb + r0 + ri] = p2 + b2[0];
        }
    }
}

/* ------------------------------------------------------------------ */
/* k2: global max of f2 (exact softmax max via monotone leaky-relu)    */
/* ------------------------------------------------------------------ */
__global__ void k2_max() {
    __shared__ float red[256];
    const int tid = threadIdx.x;
    float m = -1e30f;
    for (int i = tid; i < N_TOK; i += 256) m = fmaxf(m, g_f2[i]);
    red[tid] = m; __syncthreads();
    for (int s = 128; s > 0; s >>= 1) {
        if (tid < s) red[tid] = fmaxf(red[tid], red[tid + s]);
        __syncthreads();
    }
    if (tid == 0) g_f2max = red[0];
}

/* ------------------------------------------------------------------ */
/* k3: attention partials. grid (64 row-blocks, NSPLIT), 256 threads.  */
/* Per 128-j tile: build P in smem (exp with precomputed row max),     */
/* then fp32x2 FMA accumulation: thread owns rows {pair, pair+64},     */
/* 16 output cols (og*16..).                                           */
/* ------------------------------------------------------------------ */
__global__ __launch_bounds__(256, 2) void k3_attn(const float* __restrict__ bias) {
    extern __shared__ float sm[];
    float* Ps   = sm;                               /* 128*132 */
    float* Vs   = Ps + M_TILE * PS_STRIDE;          /* 128*68  */
    float* f1s  = Vs + J_TILE * VS_STRIDE;          /* 128 */
    float* ms   = f1s + M_TILE;                     /* 128 */
    float* f2s  = ms + M_TILE;                      /* 128 */
    float* dens = f2s + J_TILE;                     /* 128 */

    const int tid   = threadIdx.x;
    const int ibase = blockIdx.x * M_TILE;
    const int s     = blockIdx.y;
    const int jbase0 = s * JCHUNK;

    if (tid < M_TILE) {
        const float f1v = g_f1[ibase + tid];
        f1s[tid] = f1v;
        const float x = f1v + g_f2max;
        ms[tid] = fmaxf(x, 0.2f * x);   /* exact row max (bias <= 0) */
        dens[tid] = 0.f;
    }

    const int pair = tid >> 2, og = tid & 3;
    const int ia = pair, ib = pair + 64;
    unsigned long long accA[8], accB[8];
#pragma unroll
    for (int c = 0; c < 8; ++c) { accA[c] = 0ull; accB[c] = 0ull; }

    const int warp = tid >> 5, lane = tid & 31;
    const float4* bias4 = (const float4*)bias;
    float4* Ps4 = (float4*)Ps;
    const float4* Vs4 = (const float4*)Vs;
    const float4* fts4 = (const float4*)g_fts;

    for (int t = 0; t < JCHUNK / J_TILE; ++t) {
        const int jb = jbase0 + t * J_TILE;
        __syncthreads();
        /* load V tile + f2 tile */
        for (int u = tid; u < J_TILE * 16; u += 256) {
            const int j = u >> 4, c4 = u & 15;
            ((float4*)Vs)[j * 17 + c4] = fts4[(jb + j) * 16 + c4];
        }
        if (tid < J_TILE) f2s[tid] = g_f2[jb + tid];
        __syncthreads();

        /* P tile: warp w handles rows w, w+8, ..., w+120 */
#pragma unroll 4
        for (int rr = 0; rr < 16; ++rr) {
            const int i = warp + rr * 8;
            const float f1v = f1s[i];
            const float mi  = ms[i];
            const float4 f2v = ((const float4*)f2s)[lane];
            const float4 bv  = bias4[(size_t)(ibase + i) * (N_TOK / 4) + (jb >> 2) + lane];
            float4 p; float x;
            x = f1v + f2v.x; x = fmaxf(x, 0.2f * x) + bv.x; p.x = __expf(x - mi);
            x = f1v + f2v.y; x = fmaxf(x, 0.2f * x) + bv.y; p.y = __expf(x - mi);
            x = f1v + f2v.z; x = fmaxf(x, 0.2f * x) + bv.z; p.z = __expf(x - mi);
            x = f1v + f2v.w; x = fmaxf(x, 0.2f * x) + bv.w; p.w = __expf(x - mi);
            Ps4[i * (PS_STRIDE / 4) + lane] = p;
            float rs = p.x + p.y + p.z + p.w;
#pragma unroll
            for (int off = 16; off > 0; off >>= 1)
                rs += __shfl_xor_sync(0xffffffffu, rs, off);
            if (lane == 0) dens[i] += rs;
        }
        __syncthreads();

        /* FMA phase: 16 FFMA2 per j per thread */
#pragma unroll 2
        for (int j = 0; j < J_TILE; ++j) {
            const float pa = Ps[ia * PS_STRIDE + j];
            const float pb = Ps[ib * PS_STRIDE + j];
            const unsigned long long pa2 = pack2(pa, pa);
            const unsigned long long pb2 = pack2(pb, pb);
            const float4* vrow = Vs4 + j * 17 + og * 4;
#pragma unroll
            for (int q = 0; q < 4; ++q) {
                const float4 v = vrow[q];
                const unsigned long long v0 = pack2(v.x, v.y);
                const unsigned long long v1 = pack2(v.z, v.w);
                fma2(accA[q * 2],     pa2, v0);
                fma2(accA[q * 2 + 1], pa2, v1);
                fma2(accB[q * 2],     pb2, v0);
                fma2(accB[q * 2 + 1], pb2, v1);
            }
        }
    }

    /* write unnormalized partials */
    {
        float4* accOut = (float4*)g_acc;
        const size_t baseA = ((size_t)s * N_TOK + ibase + ia) * 16 + og * 4;
        const size_t baseB = ((size_t)s * N_TOK + ibase + ib) * 16 + og * 4;
#pragma unroll
        for (int q = 0; q < 4; ++q) {
            float4 o;
            unpack2(accA[q * 2],     o.x, o.y);
            unpack2(accA[q * 2 + 1], o.z, o.w);
            accOut[baseA + q] = o;
            unpack2(accB[q * 2],     o.x, o.y);
            unpack2(accB[q * 2 + 1], o.z, o.w);
            accOut[baseB + q] = o;
        }
    }
    __syncthreads();
    if (tid < M_TILE) g_den[s * N_TOK + ibase + tid] = dens[tid];
}

/* ------------------------------------------------------------------ */
/* k4: combine splits, normalize, ELU                                  */
/* ------------------------------------------------------------------ */
__global__ __launch_bounds__(256) void k4_combine(float* __restrict__ out) {
    const int idx = blockIdx.x * 256 + threadIdx.x;   /* over 131072 float4 */
    if (idx >= N_TOK * 16) return;
    const int i = idx >> 4;
    float den = 0.f;
    float4 a = make_float4(0.f, 0.f, 0.f, 0.f);
#pragma unroll
    for (int s = 0; s < NSPLIT; ++s) {
        den += g_den[s * N_TOK + i];
        const float4 p = ((const float4*)g_acc)[(size_t)s * N_TOK * 16 + idx];
        a.x += p.x; a.y += p.y; a.z += p.z; a.w += p.w;
    }
    const float inv = 1.f / den;
    float4 r = make_float4(a.x * inv, a.y * inv, a.z * inv, a.w * inv);
    r.x = r.x > 0.f ? r.x : expm1f(r.x);
    r.y = r.y > 0.f ? r.y : expm1f(r.y);
    r.z = r.z > 0.f ? r.z : expm1f(r.z);
    r.w = r.w > 0.f ? r.w : expm1f(r.w);
    ((float4*)out)[idx] = r;
}

/* ------------------------------------------------------------------ */
extern "C" void kernel_launch(void* const* d_in, const int* in_sizes, int n_in,
                              void* d_out, int out_size) {
    const float* seq  = (const float*)d_in[0];
    const float* bias = (const float*)d_in[1];
    const float* W1   = (const float*)d_in[2];
    const float* a1   = (const float*)d_in[3];
    const float* b1   = (const float*)d_in[4];
    const float* a2   = (const float*)d_in[5];
    const float* b2   = (const float*)d_in[6];
    float* out = (float*)d_out;

    const int smem3 = (M_TILE * PS_STRIDE + J_TILE * VS_STRIDE + 4 * M_TILE) * (int)sizeof(float);
    cudaFuncSetAttribute(k3_attn, cudaFuncAttributeMaxDynamicSharedMemorySize, smem3);

    k1_fts<<<128, 256>>>(seq, W1, a1, b1, a2, b2);
    k2_max<<<1, 256>>>();
    dim3 g3(N_TOK / M_TILE, NSPLIT);
    k3_attn<<<g3, 256, smem3>>>(bias);
    k4_combine<<<(N_TOK * 16) / 256, 256>>>(out);
}

// round 3
// speedup vs baseline: 1.4441x; 1.4441x over previous
#include <cuda_runtime.h>
#include <cuda_bf16.h>
#include <math.h>
#include <cstdint>

#define N_TOK 8192
#define F_DIM 256
#define OUTD  64
#define NSPLIT 2
#define JCHUNK (N_TOK / NSPLIT)   /* 4096 */
#define M_TILE 128
#define JT 64                     /* j per tile */
#define NT_PER_CTA (JCHUNK / JT)  /* 64 tiles */

/* ---------------- scratch (no allocation allowed) ---------------- */
__device__ __nv_bfloat16 g_ftsT_hi[OUTD * N_TOK];  /* [c][j] transposed */
__device__ __nv_bfloat16 g_ftsT_lo[OUTD * N_TOK];
__device__ float g_f1[N_TOK];
__device__ float g_f2[N_TOK];
__device__ float g_f2max;
__device__ float g_acc[NSPLIT * N_TOK * OUTD];     /* 4 MB */
__device__ float g_den[NSPLIT * N_TOK];

/* ---------------- helpers ---------------- */
__device__ __forceinline__ uint32_t smem_u32(const void* p) {
    uint32_t a;
    asm("{ .reg .u64 t; cvta.to.shared.u64 t, %1; cvt.u32.u64 %0, t; }" : "=r"(a) : "l"(p));
    return a;
}
__device__ __forceinline__ uint32_t cvt2bf(float a, float b) {   /* mem order [a,b] */
    uint32_t r;
    asm("cvt.rn.satfinite.bf16x2.f32 %0, %1, %2;" : "=r"(r) : "f"(b), "f"(a));
    return r;
}
__device__ __forceinline__ float bf_lo_f(uint32_t h) { return __uint_as_float(h << 16); }
__device__ __forceinline__ float bf_hi_f(uint32_t h) { return __uint_as_float(h & 0xFFFF0000u); }

__device__ __forceinline__ void ldsm4(uint32_t& r0, uint32_t& r1, uint32_t& r2, uint32_t& r3,
                                      uint32_t addr) {
    asm volatile("ldmatrix.sync.aligned.m8n8.x4.shared.b16 {%0,%1,%2,%3}, [%4];"
                 : "=r"(r0), "=r"(r1), "=r"(r2), "=r"(r3) : "r"(addr));
}
__device__ __forceinline__ void mma16816(float* d, const uint32_t* a, uint32_t b0, uint32_t b1) {
    asm volatile("mma.sync.aligned.m16n8k16.row.col.f32.bf16.bf16.f32 "
                 "{%0,%1,%2,%3},{%4,%5,%6,%7},{%8,%9},{%0,%1,%2,%3};"
                 : "+f"(d[0]), "+f"(d[1]), "+f"(d[2]), "+f"(d[3])
                 : "r"(a[0]), "r"(a[1]), "r"(a[2]), "r"(a[3]), "r"(b0), "r"(b1));
}
#define BAR_SYNC(id)   asm volatile("bar.sync %0, 256;"   :: "r"(id) : "memory")
#define BAR_ARRIVE(id) asm volatile("bar.arrive %0, 256;" :: "r"(id) : "memory")

/* ------------------------------------------------------------------ */
/* k1: seq_fts = seq @ W1 -> transposed bf16 hi/lo ; f1, f2            */
/* ------------------------------------------------------------------ */
__global__ __launch_bounds__(256) void k1_fts(const float* __restrict__ seq,
        const float* __restrict__ W1, const float* __restrict__ a1,
        const float* __restrict__ b1, const float* __restrict__ a2,
        const float* __restrict__ b2) {
    __shared__ float As[64 * 68];
    __shared__ float Bs[64 * 64];
    __shared__ float a1s[OUTD], a2s[OUTD];

    const int tid = threadIdx.x;
    const int rb  = blockIdx.x * 64;
    if (tid < OUTD) { a1s[tid] = a1[tid]; a2s[tid] = a2[tid]; }

    const int cg = tid & 15, rg = tid >> 4;
    const int r0 = rg * 4,  c0 = cg * 4;

    float acc[4][4];
#pragma unroll
    for (int i = 0; i < 4; ++i)
#pragma unroll
        for (int j = 0; j < 4; ++j) acc[i][j] = 0.f;

    const float4* seq4 = (const float4*)seq;
    const float4* W14  = (const float4*)W1;
    float4* As4 = (float4*)As;
    float4* Bs4 = (float4*)Bs;

    for (int kb = 0; kb < 4; ++kb) {
        __syncthreads();
#pragma unroll
        for (int t = tid; t < 1024; t += 256) {
            const int r = t >> 4, c4 = t & 15;
            As4[r * 17 + c4] = seq4[(rb + r) * 64 + kb * 16 + c4];
            Bs4[t]           = W14[(kb * 64 + r) * 16 + c4];
        }
        __syncthreads();
#pragma unroll
        for (int k = 0; k < 64; ++k) {
            const float4 b = Bs4[k * 16 + cg];
#pragma unroll
            for (int ri = 0; ri < 4; ++ri) {
                const float a = As[(r0 + ri) * 68 + k];
                acc[ri][0] += a * b.x; acc[ri][1] += a * b.y;
                acc[ri][2] += a * b.z; acc[ri][3] += a * b.w;
            }
        }
    }

    /* write transposed bf16 hi/lo: g_ftsT[c][row] */
#pragma unroll
    for (int ci = 0; ci < 4; ++ci) {
        const int c = c0 + ci;
        const float v0 = acc[0][ci], v1 = acc[1][ci], v2 = acc[2][ci], v3 = acc[3][ci];
        const uint32_t h01 = cvt2bf(v0, v1), h23 = cvt2bf(v2, v3);
        *(uint2*)(g_ftsT_hi + (size_t)c * N_TOK + rb + r0) = make_uint2(h01, h23);
        const float e0 = v0 - bf_lo_f(h01), e1 = v1 - bf_hi_f(h01);
        const float e2 = v2 - bf_lo_f(h23), e3 = v3 - bf_hi_f(h23);
        *(uint2*)(g_ftsT_lo + (size_t)c * N_TOK + rb + r0) =
            make_uint2(cvt2bf(e0, e1), cvt2bf(e2, e3));
    }

    /* f1 / f2 */
#pragma unroll
    for (int ri = 0; ri < 4; ++ri) {
        float p1 = acc[ri][0] * a1s[c0] + acc[ri][1] * a1s[c0 + 1]
                 + acc[ri][2] * a1s[c0 + 2] + acc[ri][3] * a1s[c0 + 3];
        float p2 = acc[ri][0] * a2s[c0] + acc[ri][1] * a2s[c0 + 1]
                 + acc[ri][2] * a2s[c0 + 2] + acc[ri][3] * a2s[c0 + 3];
#pragma unroll
        for (int off = 8; off > 0; off >>= 1) {
            p1 += __shfl_xor_sync(0xffffffffu, p1, off);
            p2 += __shfl_xor_sync(0xffffffffu, p2, off);
        }
        if (cg == 0) {
            g_f1[rb + r0 + ri] = p1 + b1[0];
            g_f2[rb + r0 + ri] = p2 + b2[0];
        }
    }
}

/* ------------------------------------------------------------------ */
__global__ void k2_max() {
    __shared__ float red[256];
    const int tid = threadIdx.x;
    float m = -1e30f;
    for (int i = tid; i < N_TOK; i += 256) m = fmaxf(m, g_f2[i]);
    red[tid] = m; __syncthreads();
    for (int s = 128; s > 0; s >>= 1) {
        if (tid < s) red[tid] = fmaxf(red[tid], red[tid + s]);
        __syncthreads();
    }
    if (tid == 0) g_f2max = red[0];
}

/* ------------------------------------------------------------------ */
/* k3: warp-specialized P-gen + mma.sync bf16x3                        */
/* warps 0-3 produce (bias+exp+bf16 split), warps 4-7 consume (HMMA)   */
/* ------------------------------------------------------------------ */
#define PSTRB 144                 /* bytes per smem tile row (72 bf16) */
#define PH_OFF 0                  /* 2 stages x 128*144 = 36864 */
#define PL_OFF 36864
#define VH_OFF 73728              /* 2 stages x 64*144 = 18432 */
#define VL_OFF 92160
#define F1S_OFF 110592
#define MS_OFF  111104
#define DENS_OFF 111616
#define SMEM3_BYTES 112640

__global__ __launch_bounds__(256, 1) void k3_attn(const float* __restrict__ bias) {
    extern __shared__ char sm[];
    const uint32_t sbase = smem_u32(sm);
    float* f1s  = (float*)(sm + F1S_OFF);
    float* ms   = (float*)(sm + MS_OFF);
    float* dens = (float*)(sm + DENS_OFF);

    const int tid  = threadIdx.x;
    const int wid  = tid >> 5, lane = tid & 31;
    const int ibase = blockIdx.x * M_TILE;
    const int s     = blockIdx.y;
    const int jbase0 = s * JCHUNK;

    if (tid < M_TILE) {
        const float f1v = g_f1[ibase + tid];
        f1s[tid] = f1v;
        const float x = f1v + g_f2max;
        ms[tid] = fmaxf(x, 0.2f * x);
        dens[tid] = 0.f;
    }
    __syncthreads();

    if (wid < 4) {
        /* ===================== PRODUCER ===================== */
        const int jq    = lane & 15;
        const int rgrp  = wid * 2 + (lane >> 4);     /* 0..7 */
        const float4* bias4 = (const float4*)bias;

        for (int t = 0; t < NT_PER_CTA; ++t) {
            const int st = t & 1;
            const int jb = jbase0 + t * JT;
            if (t >= 2) BAR_SYNC(3 + st);            /* wait empty */

            /* stage V tile: 64 cols x 64 j, bf16 hi/lo */
            char* vh = sm + VH_OFF + st * 9216;
            char* vl = sm + VL_OFF + st * 9216;
#pragma unroll
            for (int u = tid; u < 512; u += 128) {   /* 512 uint4 per buffer */
                const int c = u >> 3, q = u & 7;
                const uint4 a = *((const uint4*)(g_ftsT_hi + (size_t)c * N_TOK + jb) + q);
                const uint4 b = *((const uint4*)(g_ftsT_lo + (size_t)c * N_TOK + jb) + q);
                char* d0 = vh + c * PSTRB + q * 16;
                char* d1 = vl + c * PSTRB + q * 16;
                *(uint2*)d0       = make_uint2(a.x, a.y);
                *(uint2*)(d0 + 8) = make_uint2(a.z, a.w);
                *(uint2*)d1       = make_uint2(b.x, b.y);
                *(uint2*)(d1 + 8) = make_uint2(b.z, b.w);
            }

            /* generate P tile: 128 rows x 64 j */
            char* ph = sm + PH_OFF + st * 18432;
            char* pl = sm + PL_OFF + st * 18432;
            const float4 f2v = *((const float4*)(g_f2 + jb) + jq);
#pragma unroll 4
            for (int k = 0; k < 16; ++k) {
                const int i = rgrp + k * 8;
                const float f1v = f1s[i];
                const float cst = f1s[i] - ms[i];    /* fold -mi */
                (void)f1v;
                const float4 bv = __ldg(&bias4[(size_t)(ibase + i) * (N_TOK / 4) + (jb >> 2) + jq]);
                float x, p0, p1, p2, p3;
                x = f1s[i] + f2v.x; x = fmaxf(x, 0.2f * x) + bv.x - ms[i]; p0 = __expf(x);
                x = f1s[i] + f2v.y; x = fmaxf(x, 0.2f * x) + bv.y - ms[i]; p1 = __expf(x);
                x = f1s[i] + f2v.z; x = fmaxf(x, 0.2f * x) + bv.z - ms[i]; p2 = __expf(x);
                x = f1s[i] + f2v.w; x = fmaxf(x, 0.2f * x) + bv.w - ms[i]; p3 = __expf(x);
                (void)cst;

                const uint32_t h01 = cvt2bf(p0, p1), h23 = cvt2bf(p2, p3);
                const float e0 = p0 - bf_lo_f(h01), e1 = p1 - bf_hi_f(h01);
                const float e2 = p2 - bf_lo_f(h23), e3 = p3 - bf_hi_f(h23);
                *(uint2*)(ph + i * PSTRB + jq * 8) = make_uint2(h01, h23);
                *(uint2*)(pl + i * PSTRB + jq * 8) = make_uint2(cvt2bf(e0, e1), cvt2bf(e2, e3));

                float rs = (p0 + p1) + (p2 + p3);
                rs += __shfl_xor_sync(0xffffffffu, rs, 8);
                rs += __shfl_xor_sync(0xffffffffu, rs, 4);
                rs += __shfl_xor_sync(0xffffffffu, rs, 2);
                rs += __shfl_xor_sync(0xffffffffu, rs, 1);
                if (jq == 0) dens[i] += rs;
            }
            BAR_ARRIVE(1 + st);                      /* signal full */
        }
    } else {
        /* ===================== CONSUMER ===================== */
        const int cw = wid - 4;                      /* 0..3 */
        float acc[2][8][4];
#pragma unroll
        for (int b = 0; b < 2; ++b)
#pragma unroll
            for (int n = 0; n < 8; ++n)
#pragma unroll
                for (int q = 0; q < 4; ++q) acc[b][n][q] = 0.f;

        /* lane-dependent smem addressing (row = lane&15, col-half = lane>>4) */
        const uint32_t rsel = (uint32_t)(lane & 15) * PSTRB + (uint32_t)(lane >> 4) * 16;

        for (int t = 0; t < NT_PER_CTA; ++t) {
            const int st = t & 1;
            BAR_SYNC(1 + st);                        /* wait full */

            const uint32_t ph = sbase + PH_OFF + st * 18432;
            const uint32_t pl = sbase + PL_OFF + st * 18432;
            const uint32_t vh = sbase + VH_OFF + st * 9216;
            const uint32_t vl = sbase + VL_OFF + st * 9216;

#pragma unroll
            for (int ks = 0; ks < 4; ++ks) {
                const uint32_t kofs = (uint32_t)ks * 32;   /* 16 bf16 = 32B */
                uint32_t ah0[4], al0[4], ah1[4], al1[4];
                ldsm4(ah0[0], ah0[1], ah0[2], ah0[3],
                      ph + (cw * 32) * PSTRB + kofs + rsel);
                ldsm4(al0[0], al0[1], al0[2], al0[3],
                      pl + (cw * 32) * PSTRB + kofs + rsel);
                ldsm4(ah1[0], ah1[1], ah1[2], ah1[3],
                      ph + (cw * 32 + 16) * PSTRB + kofs + rsel);
                ldsm4(al1[0], al1[1], al1[2], al1[3],
                      pl + (cw * 32 + 16) * PSTRB + kofs + rsel);
#pragma unroll
                for (int np = 0; np < 4; ++np) {
                    uint32_t bh[4], bl[4];
                    ldsm4(bh[0], bh[1], bh[2], bh[3],
                          vh + (np * 16) * PSTRB + kofs + rsel);
                    ldsm4(bl[0], bl[1], bl[2], bl[3],
                          vl + (np * 16) * PSTRB + kofs + rsel);
                    /* n-tile 2np uses (r0,r2); 2np+1 uses (r1,r3) */
                    mma16816(acc[0][np * 2],     ah0, bh[0], bh[2]);
                    mma16816(acc[0][np * 2],     ah0, bl[0], bl[2]);
                    mma16816(acc[0][np * 2],     al0, bh[0], bh[2]);
                    mma16816(acc[0][np * 2 + 1], ah0, bh[1], bh[3]);
                    mma16816(acc[0][np * 2 + 1], ah0, bl[1], bl[3]);
                    mma16816(acc[0][np * 2 + 1], al0, bh[1], bh[3]);
                    mma16816(acc[1][np * 2],     ah1, bh[0], bh[2]);
                    mma16816(acc[1][np * 2],     ah1, bl[0], bl[2]);
                    mma16816(acc[1][np * 2],     al1, bh[0], bh[2]);
                    mma16816(acc[1][np * 2 + 1], ah1, bh[1], bh[3]);
                    mma16816(acc[1][np * 2 + 1], ah1, bl[1], bl[3]);
                    mma16816(acc[1][np * 2 + 1], al1, bh[1], bh[3]);
                }
            }
            BAR_ARRIVE(3 + st);                      /* signal empty */
        }

        /* write partials: acc is unnormalized P@V for rows cw*32..cw*32+32 */
#pragma unroll
        for (int b = 0; b < 2; ++b) {
            const int m = cw * 32 + b * 16 + (lane >> 2);
            float* dst0 = g_acc + ((size_t)s * N_TOK + ibase + m) * OUTD;
            float* dst8 = dst0 + 8 * OUTD;
#pragma unroll
            for (int n = 0; n < 8; ++n) {
                const int c = n * 8 + (lane & 3) * 2;
                *(float2*)(dst0 + c) = make_float2(acc[b][n][0], acc[b][n][1]);
                *(float2*)(dst8 + c) = make_float2(acc[b][n][2], acc[b][n][3]);
            }
        }
    }

    __syncthreads();
    if (tid < M_TILE) g_den[s * N_TOK + ibase + tid] = dens[tid];
}

/* ------------------------------------------------------------------ */
__global__ __launch_bounds__(256) void k4_combine(float* __restrict__ out) {
    const int idx = blockIdx.x * 256 + threadIdx.x;
    if (idx >= N_TOK * 16) return;
    const int i = idx >> 4;
    float den = 0.f;
    float4 a = make_float4(0.f, 0.f, 0.f, 0.f);
#pragma unroll
    for (int s = 0; s < NSPLIT; ++s) {
        den += g_den[s * N_TOK + i];
        const float4 p = ((const float4*)g_acc)[(size_t)s * N_TOK * 16 + idx];
        a.x += p.x; a.y += p.y; a.z += p.z; a.w += p.w;
    }
    const float inv = 1.f / den;
    float4 r = make_float4(a.x * inv, a.y * inv, a.z * inv, a.w * inv);
    r.x = r.x > 0.f ? r.x : expm1f(r.x);
    r.y = r.y > 0.f ? r.y : expm1f(r.y);
    r.z = r.z > 0.f ? r.z : expm1f(r.z);
    r.w = r.w > 0.f ? r.w : expm1f(r.w);
    ((float4*)out)[idx] = r;
}

/* ------------------------------------------------------------------ */
extern "C" void kernel_launch(void* const* d_in, const int* in_sizes, int n_in,
                              void* d_out, int out_size) {
    const float* seq  = (const float*)d_in[0];
    const float* bias = (const float*)d_in[1];
    const float* W1   = (const float*)d_in[2];
    const float* a1   = (const float*)d_in[3];
    const float* b1   = (const float*)d_in[4];
    const float* a2   = (const float*)d_in[5];
    const float* b2   = (const float*)d_in[6];
    float* out = (float*)d_out;

    cudaFuncSetAttribute(k3_attn, cudaFuncAttributeMaxDynamicSharedMemorySize, SMEM3_BYTES);

    k1_fts<<<128, 256>>>(seq, W1, a1, b1, a2, b2);
    k2_max<<<1, 256>>>();
    dim3 g3(N_TOK / M_TILE, NSPLIT);
    k3_attn<<<g3, 256, SMEM3_BYTES>>>(bias);
    k4_combine<<<(N_TOK * 16) / 256, 256>>>(out);
}

// round 4
// speedup vs baseline: 2.8083x; 1.9447x over previous
#include <cuda_runtime.h>
#include <cuda_bf16.h>
#include <math.h>
#include <cstdint>

#define N_TOK 8192
#define F_DIM 256
#define OUTD  64
#define NSPLIT 2
#define JCHUNK (N_TOK / NSPLIT)   /* 4096 */
#define M_TILE 128
#define JT 64                     /* j per tile */
#define NT_PER_CTA (JCHUNK / JT)  /* 64 tiles */

/* ---------------- scratch (no allocation allowed) ---------------- */
__device__ __nv_bfloat16 g_ftsT_hi[OUTD * N_TOK];  /* [c][j] transposed */
__device__ __nv_bfloat16 g_ftsT_lo[OUTD * N_TOK];
__device__ float g_f1[N_TOK];
__device__ float g_f2[N_TOK];
__device__ float g_f2max;
__device__ float g_acc[NSPLIT * N_TOK * OUTD];     /* 4 MB */
__device__ float g_den[NSPLIT * N_TOK];

/* ---------------- helpers ---------------- */
__device__ __forceinline__ uint32_t smem_u32(const void* p) {
    uint32_t a;
    asm("{ .reg .u64 t; cvta.to.shared.u64 t, %1; cvt.u32.u64 %0, t; }" : "=r"(a) : "l"(p));
    return a;
}
__device__ __forceinline__ uint32_t cvt2bf(float a, float b) {   /* mem order [a,b] */
    uint32_t r;
    asm("cvt.rn.satfinite.bf16x2.f32 %0, %1, %2;" : "=r"(r) : "f"(b), "f"(a));
    return r;
}
__device__ __forceinline__ float bf_lo_f(uint32_t h) { return __uint_as_float(h << 16); }
__device__ __forceinline__ float bf_hi_f(uint32_t h) { return __uint_as_float(h & 0xFFFF0000u); }

__device__ __forceinline__ void ldsm4(uint32_t& r0, uint32_t& r1, uint32_t& r2, uint32_t& r3,
                                      uint32_t addr) {
    asm volatile("ldmatrix.sync.aligned.m8n8.x4.shared.b16 {%0,%1,%2,%3}, [%4];"
                 : "=r"(r0), "=r"(r1), "=r"(r2), "=r"(r3) : "r"(addr));
}
__device__ __forceinline__ void mma16816(float* d, const uint32_t* a, uint32_t b0, uint32_t b1) {
    asm volatile("mma.sync.aligned.m16n8k16.row.col.f32.bf16.bf16.f32 "
                 "{%0,%1,%2,%3},{%4,%5,%6,%7},{%8,%9},{%0,%1,%2,%3};"
                 : "+f"(d[0]), "+f"(d[1]), "+f"(d[2]), "+f"(d[3])
                 : "r"(a[0]), "r"(a[1]), "r"(a[2]), "r"(a[3]), "r"(b0), "r"(b1));
}
#define BAR_SYNC(id)   asm volatile("bar.sync %0, 256;"   :: "r"(id) : "memory")
#define BAR_ARRIVE(id) asm volatile("bar.arrive %0, 256;" :: "r"(id) : "memory")
#define BARH_SYNC(id)  asm volatile("bar.sync %0, 128;"   :: "r"(id) : "memory")
#define CP_ASYNC16(dst, src) \
    asm volatile("cp.async.cg.shared.global [%0], [%1], 16;" :: "r"(dst), "l"(src) : "memory")
#define CP_COMMIT() asm volatile("cp.async.commit_group;" ::: "memory")
#define CP_WAIT1()  asm volatile("cp.async.wait_group 1;" ::: "memory")

/* ------------------------------------------------------------------ */
/* k1: seq_fts = seq @ W1 -> transposed bf16 hi/lo ; f1, f2            */
/* ------------------------------------------------------------------ */
__global__ __launch_bounds__(256) void k1_fts(const float* __restrict__ seq,
        const float* __restrict__ W1, const float* __restrict__ a1,
        const float* __restrict__ b1, const float* __restrict__ a2,
        const float* __restrict__ b2) {
    __shared__ float As[64 * 68];
    __shared__ float Bs[64 * 64];
    __shared__ float a1s[OUTD], a2s[OUTD];

    const int tid = threadIdx.x;
    const int rb  = blockIdx.x * 64;
    if (tid < OUTD) { a1s[tid] = a1[tid]; a2s[tid] = a2[tid]; }

    const int cg = tid & 15, rg = tid >> 4;
    const int r0 = rg * 4,  c0 = cg * 4;

    float acc[4][4];
#pragma unroll
    for (int i = 0; i < 4; ++i)
#pragma unroll
        for (int j = 0; j < 4; ++j) acc[i][j] = 0.f;

    const float4* seq4 = (const float4*)seq;
    const float4* W14  = (const float4*)W1;
    float4* As4 = (float4*)As;
    float4* Bs4 = (float4*)Bs;

    for (int kb = 0; kb < 4; ++kb) {
        __syncthreads();
#pragma unroll
        for (int t = tid; t < 1024; t += 256) {
            const int r = t >> 4, c4 = t & 15;
            As4[r * 17 + c4] = seq4[(rb + r) * 64 + kb * 16 + c4];
            Bs4[t]           = W14[(kb * 64 + r) * 16 + c4];
        }
        __syncthreads();
#pragma unroll
        for (int k = 0; k < 64; ++k) {
            const float4 b = Bs4[k * 16 + cg];
#pragma unroll
            for (int ri = 0; ri < 4; ++ri) {
                const float a = As[(r0 + ri) * 68 + k];
                acc[ri][0] += a * b.x; acc[ri][1] += a * b.y;
                acc[ri][2] += a * b.z; acc[ri][3] += a * b.w;
            }
        }
    }

    /* write transposed bf16 hi/lo: g_ftsT[c][row] */
#pragma unroll
    for (int ci = 0; ci < 4; ++ci) {
        const int c = c0 + ci;
        const float v0 = acc[0][ci], v1 = acc[1][ci], v2 = acc[2][ci], v3 = acc[3][ci];
        const uint32_t h01 = cvt2bf(v0, v1), h23 = cvt2bf(v2, v3);
        *(uint2*)(g_ftsT_hi + (size_t)c * N_TOK + rb + r0) = make_uint2(h01, h23);
        const float e0 = v0 - bf_lo_f(h01), e1 = v1 - bf_hi_f(h01);
        const float e2 = v2 - bf_lo_f(h23), e3 = v3 - bf_hi_f(h23);
        *(uint2*)(g_ftsT_lo + (size_t)c * N_TOK + rb + r0) =
            make_uint2(cvt2bf(e0, e1), cvt2bf(e2, e3));
    }

    /* f1 / f2 */
#pragma unroll
    for (int ri = 0; ri < 4; ++ri) {
        float p1 = acc[ri][0] * a1s[c0] + acc[ri][1] * a1s[c0 + 1]
                 + acc[ri][2] * a1s[c0 + 2] + acc[ri][3] * a1s[c0 + 3];
        float p2 = acc[ri][0] * a2s[c0] + acc[ri][1] * a2s[c0 + 1]
                 + acc[ri][2] * a2s[c0 + 2] + acc[ri][3] * a2s[c0 + 3];
#pragma unroll
        for (int off = 8; off > 0; off >>= 1) {
            p1 += __shfl_xor_sync(0xffffffffu, p1, off);
            p2 += __shfl_xor_sync(0xffffffffu, p2, off);
        }
        if (cg == 0) {
            g_f1[rb + r0 + ri] = p1 + b1[0];
            g_f2[rb + r0 + ri] = p2 + b2[0];
        }
    }
}

/* ------------------------------------------------------------------ */
__global__ void k2_max() {
    __shared__ float red[256];
    const int tid = threadIdx.x;
    float m = -1e30f;
    for (int i = tid; i < N_TOK; i += 256) m = fmaxf(m, g_f2[i]);
    red[tid] = m; __syncthreads();
    for (int s = 128; s > 0; s >>= 1) {
        if (tid < s) red[tid] = fmaxf(red[tid], red[tid + s]);
        __syncthreads();
    }
    if (tid == 0) g_f2max = red[0];
}

/* ------------------------------------------------------------------ */
/* k3: warp-specialized P-gen + mma.sync bf16x3                        */
/* warps 0-3: bias cp.async ring + P-gen; warps 4-7: V stage + HMMA    */
/* ------------------------------------------------------------------ */
#define PSTRB 144                 /* bytes per smem tile row (72 bf16) */
#define PH_OFF 0                  /* 2 stages x 128*144 = 36864 */
#define PL_OFF 36864
#define VH_OFF 73728              /* single stage 64*144 = 9216 */
#define VL_OFF 82944
#define F1S_OFF 92160
#define MS_OFF  92672
#define DENS_OFF 93184
#define BIAS_OFF 93696            /* 3 stages x 32768 */
#define BIAS_STG 32768
#define SMEM3_BYTES (BIAS_OFF + 3 * BIAS_STG)   /* 192000 */

__global__ __launch_bounds__(256, 1) void k3_attn(const float* __restrict__ bias) {
    extern __shared__ char sm[];
    const uint32_t sbase = smem_u32(sm);
    float* f1s  = (float*)(sm + F1S_OFF);
    float* ms   = (float*)(sm + MS_OFF);
    float* dens = (float*)(sm + DENS_OFF);

    const int tid  = threadIdx.x;
    const int wid  = tid >> 5, lane = tid & 31;
    const int ibase = blockIdx.x * M_TILE;
    const int s     = blockIdx.y;
    const int jbase0 = s * JCHUNK;

    if (tid < M_TILE) {
        const float f1v = g_f1[ibase + tid];
        f1s[tid] = f1v;
        const float x = f1v + g_f2max;
        ms[tid] = fmaxf(x, 0.2f * x);
        dens[tid] = 0.f;
    }
    __syncthreads();

    if (wid < 4) {
        /* ===================== PRODUCER ===================== */
        const int jq    = lane & 15;
        const int rgrp  = wid * 2 + (lane >> 4);     /* 0..7 */

        /* prologue: prefetch bias tiles 0 and 1 */
#pragma unroll
        for (int pt = 0; pt < 2; ++pt) {
            const int jb2 = jbase0 + pt * JT;
            const uint32_t dbase = sbase + BIAS_OFF + pt * BIAS_STG;
#pragma unroll
            for (int q = 0; q < 16; ++q) {
                const int u = q * 128 + tid;
                const int row = u >> 4, c4 = u & 15;
                CP_ASYNC16(dbase + row * 256 + c4 * 16,
                           bias + (size_t)(ibase + row) * N_TOK + jb2 + c4 * 4);
            }
            CP_COMMIT();
        }

        for (int t = 0; t < NT_PER_CTA; ++t) {
            const int st = t & 1;
            const int jb = jbase0 + t * JT;
            if (t >= 2) BAR_SYNC(3 + st);            /* P buffers empty */

            CP_WAIT1();                               /* bias tile t landed (mine) */
            BARH_SYNC(5);                             /* all producers: visible + safe slot reuse */

            /* prefetch bias tile t+2 */
            if (t + 2 < NT_PER_CTA) {
                const int slot = (t + 2) % 3;
                const int jb2 = jbase0 + (t + 2) * JT;
                const uint32_t dbase = sbase + BIAS_OFF + slot * BIAS_STG;
#pragma unroll
                for (int q = 0; q < 16; ++q) {
                    const int u = q * 128 + tid;
                    const int row = u >> 4, c4 = u & 15;
                    CP_ASYNC16(dbase + row * 256 + c4 * 16,
                               bias + (size_t)(ibase + row) * N_TOK + jb2 + c4 * 4);
                }
            }
            CP_COMMIT();

            /* generate P tile: 128 rows x 64 j (bias from smem ring) */
            char* ph = sm + PH_OFF + st * 18432;
            char* pl = sm + PL_OFF + st * 18432;
            const char* bslot = sm + BIAS_OFF + (t % 3) * BIAS_STG;
            const float4 f2v = *((const float4*)(g_f2 + jb) + jq);
#pragma unroll 4
            for (int k = 0; k < 16; ++k) {
                const int i = rgrp + k * 8;
                const float f1v = f1s[i];
                const float mi  = ms[i];
                const float4 bv = *(const float4*)(bslot + i * 256 + jq * 16);
                float x, p0, p1, p2, p3;
                x = f1v + f2v.x; x = fmaxf(x, 0.2f * x) + bv.x - mi; p0 = __expf(x);
                x = f1v + f2v.y; x = fmaxf(x, 0.2f * x) + bv.y - mi; p1 = __expf(x);
                x = f1v + f2v.z; x = fmaxf(x, 0.2f * x) + bv.z - mi; p2 = __expf(x);
                x = f1v + f2v.w; x = fmaxf(x, 0.2f * x) + bv.w - mi; p3 = __expf(x);

                const uint32_t h01 = cvt2bf(p0, p1), h23 = cvt2bf(p2, p3);
                const float e0 = p0 - bf_lo_f(h01), e1 = p1 - bf_hi_f(h01);
                const float e2 = p2 - bf_lo_f(h23), e3 = p3 - bf_hi_f(h23);
                *(uint2*)(ph + i * PSTRB + jq * 8) = make_uint2(h01, h23);
                *(uint2*)(pl + i * PSTRB + jq * 8) = make_uint2(cvt2bf(e0, e1), cvt2bf(e2, e3));

                float rs = (p0 + p1) + (p2 + p3);
                rs += __shfl_xor_sync(0xffffffffu, rs, 8);
                rs += __shfl_xor_sync(0xffffffffu, rs, 4);
                rs += __shfl_xor_sync(0xffffffffu, rs, 2);
                rs += __shfl_xor_sync(0xffffffffu, rs, 1);
                if (jq == 0) dens[i] += rs;
            }
            BAR_ARRIVE(1 + st);                      /* signal P full */
        }
    } else {
        /* ===================== CONSUMER ===================== */
        const int cw   = wid - 4;                    /* 0..3 */
        const int ctid = tid - 128;                  /* 0..127 */
        float acc[2][8][4];
#pragma unroll
        for (int b = 0; b < 2; ++b)
#pragma unroll
            for (int n = 0; n < 8; ++n)
#pragma unroll
                for (int q = 0; q < 4; ++q) acc[b][n][q] = 0.f;

        const uint32_t rsel = (uint32_t)(lane & 15) * PSTRB + (uint32_t)(lane >> 4) * 16;
        const uint32_t vhb = sbase + VH_OFF;
        const uint32_t vlb = sbase + VL_OFF;

        for (int t = 0; t < NT_PER_CTA; ++t) {
            const int st = t & 1;
            const int jb = jbase0 + t * JT;

            /* issue V loads early (latency hides under the full-wait) */
            uint4 vh_r[4], vl_r[4];
#pragma unroll
            for (int r = 0; r < 4; ++r) {
                const int u = r * 128 + ctid;
                const int c = u >> 3, q = u & 7;
                vh_r[r] = *((const uint4*)(g_ftsT_hi + (size_t)c * N_TOK + jb) + q);
                vl_r[r] = *((const uint4*)(g_ftsT_lo + (size_t)c * N_TOK + jb) + q);
            }

            BAR_SYNC(1 + st);                        /* P full; all consumers past t-1 */

            /* stage V into (single) smem buffer */
#pragma unroll
            for (int r = 0; r < 4; ++r) {
                const int u = r * 128 + ctid;
                const int c = u >> 3, q = u & 7;
                *(uint4*)(sm + VH_OFF + c * PSTRB + q * 16) = vh_r[r];
                *(uint4*)(sm + VL_OFF + c * PSTRB + q * 16) = vl_r[r];
            }
            BARH_SYNC(7);                            /* V visible to all consumers */

            const uint32_t ph = sbase + PH_OFF + st * 18432;
            const uint32_t pl = sbase + PL_OFF + st * 18432;

#pragma unroll
            for (int ks = 0; ks < 4; ++ks) {
                const uint32_t kofs = (uint32_t)ks * 32;   /* 16 bf16 = 32B */
                uint32_t ah0[4], al0[4], ah1[4], al1[4];
                ldsm4(ah0[0], ah0[1], ah0[2], ah0[3],
                      ph + (cw * 32) * PSTRB + kofs + rsel);
                ldsm4(al0[0], al0[1], al0[2], al0[3],
                      pl + (cw * 32) * PSTRB + kofs + rsel);
                ldsm4(ah1[0], ah1[1], ah1[2], ah1[3],
                      ph + (cw * 32 + 16) * PSTRB + kofs + rsel);
                ldsm4(al1[0], al1[1], al1[2], al1[3],
                      pl + (cw * 32 + 16) * PSTRB + kofs + rsel);
#pragma unroll
                for (int np = 0; np < 4; ++np) {
                    uint32_t bh[4], bl[4];
                    ldsm4(bh[0], bh[1], bh[2], bh[3],
                          vhb + (np * 16) * PSTRB + kofs + rsel);
                    ldsm4(bl[0], bl[1], bl[2], bl[3],
                          vlb + (np * 16) * PSTRB + kofs + rsel);
                    mma16816(acc[0][np * 2],     ah0, bh[0], bh[2]);
                    mma16816(acc[0][np * 2],     ah0, bl[0], bl[2]);
                    mma16816(acc[0][np * 2],     al0, bh[0], bh[2]);
                    mma16816(acc[0][np * 2 + 1], ah0, bh[1], bh[3]);
                    mma16816(acc[0][np * 2 + 1], ah0, bl[1], bl[3]);
                    mma16816(acc[0][np * 2 + 1], al0, bh[1], bh[3]);
                    mma16816(acc[1][np * 2],     ah1, bh[0], bh[2]);
                    mma16816(acc[1][np * 2],     ah1, bl[0], bl[2]);
                    mma16816(acc[1][np * 2],     al1, bh[0], bh[2]);
                    mma16816(acc[1][np * 2 + 1], ah1, bh[1], bh[3]);
                    mma16816(acc[1][np * 2 + 1], ah1, bl[1], bl[3]);
                    mma16816(acc[1][np * 2 + 1], al1, bh[1], bh[3]);
                }
            }
            BAR_ARRIVE(3 + st);                      /* signal P empty */
        }

        /* write partials */
#pragma unroll
        for (int b = 0; b < 2; ++b) {
            const int m = cw * 32 + b * 16 + (lane >> 2);
            float* dst0 = g_acc + ((size_t)s * N_TOK + ibase + m) * OUTD;
            float* dst8 = dst0 + 8 * OUTD;
#pragma unroll
            for (int n = 0; n < 8; ++n) {
                const int c = n * 8 + (lane & 3) * 2;
                *(float2*)(dst0 + c) = make_float2(acc[b][n][0], acc[b][n][1]);
                *(float2*)(dst8 + c) = make_float2(acc[b][n][2], acc[b][n][3]);
            }
        }
    }

    __syncthreads();
    if (tid < M_TILE) g_den[s * N_TOK + ibase + tid] = dens[tid];
}

/* ------------------------------------------------------------------ */
__global__ __launch_bounds__(256) void k4_combine(float* __restrict__ out) {
    const int idx = blockIdx.x * 256 + threadIdx.x;
    if (idx >= N_TOK * 16) return;
    const int i = idx >> 4;
    float den = 0.f;
    float4 a = make_float4(0.f, 0.f, 0.f, 0.f);
#pragma unroll
    for (int s = 0; s < NSPLIT; ++s) {
        den += g_den[s * N_TOK + i];
        const float4 p = ((const float4*)g_acc)[(size_t)s * N_TOK * 16 + idx];
        a.x += p.x; a.y += p.y; a.z += p.z; a.w += p.w;
    }
    const float inv = 1.f / den;
    float4 r = make_float4(a.x * inv, a.y * inv, a.z * inv, a.w * inv);
    r.x = r.x > 0.f ? r.x : expm1f(r.x);
    r.y = r.y > 0.f ? r.y : expm1f(r.y);
    r.z = r.z > 0.f ? r.z : expm1f(r.z);
    r.w = r.w > 0.f ? r.w : expm1f(r.w);
    ((float4*)out)[idx] = r;
}

/* ------------------------------------------------------------------ */
extern "C" void kernel_launch(void* const* d_in, const int* in_sizes, int n_in,
                              void* d_out, int out_size) {
    const float* seq  = (const float*)d_in[0];
    const float* bias = (const float*)d_in[1];
    const float* W1   = (const float*)d_in[2];
    const float* a1   = (const float*)d_in[3];
    const float* b1   = (const float*)d_in[4];
    const float* a2   = (const float*)d_in[5];
    const float* b2   = (const float*)d_in[6];
    float* out = (float*)d_out;

    cudaFuncSetAttribute(k3_attn, cudaFuncAttributeMaxDynamicSharedMemorySize, SMEM3_BYTES);

    k1_fts<<<128, 256>>>(seq, W1, a1, b1, a2, b2);
    k2_max<<<1, 256>>>();
    dim3 g3(N_TOK / M_TILE, NSPLIT);
    k3_attn<<<g3, 256, SMEM3_BYTES>>>(bias);
    k4_combine<<<(N_TOK * 16) / 256, 256>>>(out);
}

// round 5
// speedup vs baseline: 2.9428x; 1.0479x over previous
#include <cuda_runtime.h>
#include <cuda_bf16.h>
#include <cuda_fp16.h>
#include <math.h>
#include <cstdint>

#define N_TOK 8192
#define F_DIM 256
#define OUTD  64
#define NSPLIT 2
#define JCHUNK (N_TOK / NSPLIT)   /* 4096 */
#define M_TILE 128
#define JT 64                     /* j per tile */
#define NT_PER_CTA (JCHUNK / JT)  /* 64 tiles */

/* ---------------- scratch (no allocation allowed) ---------------- */
__device__ __half g_ftsT[OUTD * N_TOK];            /* [c][j] transposed f16 */
__device__ float g_f1[N_TOK];
__device__ float g_f2[N_TOK];
__device__ float g_f2max;
__device__ float g_acc[NSPLIT * N_TOK * OUTD];     /* 4 MB */
__device__ float g_den[NSPLIT * N_TOK];

/* ---------------- helpers ---------------- */
__device__ __forceinline__ uint32_t smem_u32(const void* p) {
    uint32_t a;
    asm("{ .reg .u64 t; cvta.to.shared.u64 t, %1; cvt.u32.u64 %0, t; }" : "=r"(a) : "l"(p));
    return a;
}
/* pack two fp32 -> f16x2, memory order [a, b] */
__device__ __forceinline__ uint32_t cvt2h(float a, float b) {
    uint32_t r;
    asm("cvt.rn.f16x2.f32 %0, %1, %2;" : "=r"(r) : "f"(b), "f"(a));
    return r;
}
__device__ __forceinline__ void ldsm4(uint32_t& r0, uint32_t& r1, uint32_t& r2, uint32_t& r3,
                                      uint32_t addr) {
    asm volatile("ldmatrix.sync.aligned.m8n8.x4.shared.b16 {%0,%1,%2,%3}, [%4];"
                 : "=r"(r0), "=r"(r1), "=r"(r2), "=r"(r3) : "r"(addr));
}
__device__ __forceinline__ void mma16816(float* d, const uint32_t* a, uint32_t b0, uint32_t b1) {
    asm volatile("mma.sync.aligned.m16n8k16.row.col.f32.f16.f16.f32 "
                 "{%0,%1,%2,%3},{%4,%5,%6,%7},{%8,%9},{%0,%1,%2,%3};"
                 : "+f"(d[0]), "+f"(d[1]), "+f"(d[2]), "+f"(d[3])
                 : "r"(a[0]), "r"(a[1]), "r"(a[2]), "r"(a[3]), "r"(b0), "r"(b1));
}
#define BAR_SYNC(id)   asm volatile("bar.sync %0, 256;"   :: "r"(id) : "memory")
#define BAR_ARRIVE(id) asm volatile("bar.arrive %0, 256;" :: "r"(id) : "memory")
#define BARH_SYNC(id)  asm volatile("bar.sync %0, 128;"   :: "r"(id) : "memory")
#define CP_ASYNC16(dst, src) \
    asm volatile("cp.async.cg.shared.global [%0], [%1], 16;" :: "r"(dst), "l"(src) : "memory")
#define CP_COMMIT() asm volatile("cp.async.commit_group;" ::: "memory")
#define CP_WAIT2()  asm volatile("cp.async.wait_group 2;" ::: "memory")

/* ------------------------------------------------------------------ */
/* k1: seq_fts = seq @ W1 -> transposed f16 ; f1, f2                   */
/* ------------------------------------------------------------------ */
__global__ __launch_bounds__(256) void k1_fts(const float* __restrict__ seq,
        const float* __restrict__ W1, const float* __restrict__ a1,
        const float* __restrict__ b1, const float* __restrict__ a2,
        const float* __restrict__ b2) {
    __shared__ float As[64 * 68];
    __shared__ float Bs[64 * 64];
    __shared__ float a1s[OUTD], a2s[OUTD];

    const int tid = threadIdx.x;
    const int rb  = blockIdx.x * 64;
    if (tid < OUTD) { a1s[tid] = a1[tid]; a2s[tid] = a2[tid]; }

    const int cg = tid & 15, rg = tid >> 4;
    const int r0 = rg * 4,  c0 = cg * 4;

    float acc[4][4];
#pragma unroll
    for (int i = 0; i < 4; ++i)
#pragma unroll
        for (int j = 0; j < 4; ++j) acc[i][j] = 0.f;

    const float4* seq4 = (const float4*)seq;
    const float4* W14  = (const float4*)W1;
    float4* As4 = (float4*)As;
    float4* Bs4 = (float4*)Bs;

    for (int kb = 0; kb < 4; ++kb) {
        __syncthreads();
#pragma unroll
        for (int t = tid; t < 1024; t += 256) {
            const int r = t >> 4, c4 = t & 15;
            As4[r * 17 + c4] = seq4[(rb + r) * 64 + kb * 16 + c4];
            Bs4[t]           = W14[(kb * 64 + r) * 16 + c4];
        }
        __syncthreads();
#pragma unroll
        for (int k = 0; k < 64; ++k) {
            const float4 b = Bs4[k * 16 + cg];
#pragma unroll
            for (int ri = 0; ri < 4; ++ri) {
                const float a = As[(r0 + ri) * 68 + k];
                acc[ri][0] += a * b.x; acc[ri][1] += a * b.y;
                acc[ri][2] += a * b.z; acc[ri][3] += a * b.w;
            }
        }
    }

    /* write transposed f16: g_ftsT[c][row] */
#pragma unroll
    for (int ci = 0; ci < 4; ++ci) {
        const int c = c0 + ci;
        *(uint2*)(g_ftsT + (size_t)c * N_TOK + rb + r0) =
            make_uint2(cvt2h(acc[0][ci], acc[1][ci]), cvt2h(acc[2][ci], acc[3][ci]));
    }

    /* f1 / f2 */
#pragma unroll
    for (int ri = 0; ri < 4; ++ri) {
        float p1 = acc[ri][0] * a1s[c0] + acc[ri][1] * a1s[c0 + 1]
                 + acc[ri][2] * a1s[c0 + 2] + acc[ri][3] * a1s[c0 + 3];
        float p2 = acc[ri][0] * a2s[c0] + acc[ri][1] * a2s[c0 + 1]
                 + acc[ri][2] * a2s[c0 + 2] + acc[ri][3] * a2s[c0 + 3];
#pragma unroll
        for (int off = 8; off > 0; off >>= 1) {
            p1 += __shfl_xor_sync(0xffffffffu, p1, off);
            p2 += __shfl_xor_sync(0xffffffffu, p2, off);
        }
        if (cg == 0) {
            g_f1[rb + r0 + ri] = p1 + b1[0];
            g_f2[rb + r0 + ri] = p2 + b2[0];
        }
    }
}

/* ------------------------------------------------------------------ */
__global__ void k2_max() {
    __shared__ float red[256];
    const int tid = threadIdx.x;
    float m = -1e30f;
    for (int i = tid; i < N_TOK; i += 256) m = fmaxf(m, g_f2[i]);
    red[tid] = m; __syncthreads();
    for (int s = 128; s > 0; s >>= 1) {
        if (tid < s) red[tid] = fmaxf(red[tid], red[tid + s]);
        __syncthreads();
    }
    if (tid == 0) g_f2max = red[0];
}

/* ------------------------------------------------------------------ */
/* k3: warp-specialized P-gen + single f16 mma.sync                    */
/* warps 0-3: bias cp.async ring + P-gen; warps 4-7: V stage + HMMA    */
/* ------------------------------------------------------------------ */
#define PSTRB 144                 /* bytes per smem tile row (72 f16) */
#define PH_OFF 0                  /* 2 stages x 128*144 = 36864 */
#define VH_OFF 36864              /* single stage 64*144 = 9216 */
#define F1S_OFF 46080
#define MS_OFF  46592
#define DENS_OFF 47104
#define BIAS_OFF 47616            /* 4 stages x 32768 */
#define BIAS_STG 32768
#define SMEM3_BYTES (BIAS_OFF + 4 * BIAS_STG)   /* 178688 */

__global__ __launch_bounds__(256, 1) void k3_attn(const float* __restrict__ bias) {
    extern __shared__ char sm[];
    const uint32_t sbase = smem_u32(sm);
    float* f1s  = (float*)(sm + F1S_OFF);
    float* ms   = (float*)(sm + MS_OFF);
    float* dens = (float*)(sm + DENS_OFF);

    const int tid  = threadIdx.x;
    const int wid  = tid >> 5, lane = tid & 31;
    const int ibase = blockIdx.x * M_TILE;
    const int s     = blockIdx.y;
    const int jbase0 = s * JCHUNK;

    if (tid < M_TILE) {
        const float f1v = g_f1[ibase + tid];
        f1s[tid] = f1v;
        const float x = f1v + g_f2max;
        ms[tid] = fmaxf(x, 0.2f * x);
        dens[tid] = 0.f;
    }
    __syncthreads();

    if (wid < 4) {
        /* ===================== PRODUCER ===================== */
        const int jq    = lane & 15;
        const int rgrp  = wid * 2 + (lane >> 4);     /* 0..7 */

        /* prologue: prefetch bias tiles 0,1,2 */
#pragma unroll
        for (int pt = 0; pt < 3; ++pt) {
            const int jb2 = jbase0 + pt * JT;
            const uint32_t dbase = sbase + BIAS_OFF + pt * BIAS_STG;
#pragma unroll
            for (int q = 0; q < 16; ++q) {
                const int u = q * 128 + tid;
                const int row = u >> 4, c4 = u & 15;
                CP_ASYNC16(dbase + row * 256 + c4 * 16,
                           bias + (size_t)(ibase + row) * N_TOK + jb2 + c4 * 4);
            }
            CP_COMMIT();
        }

        for (int t = 0; t < NT_PER_CTA; ++t) {
            const int st = t & 1;
            const int jb = jbase0 + t * JT;
            if (t >= 2) BAR_SYNC(3 + st);            /* P buffer empty */

            CP_WAIT2();                               /* bias tile t landed (mine) */
            BARH_SYNC(5);                             /* all producers: visible + slot reuse */

            /* prefetch bias tile t+3 */
            if (t + 3 < NT_PER_CTA) {
                const int slot = (t + 3) & 3;
                const int jb2 = jbase0 + (t + 3) * JT;
                const uint32_t dbase = sbase + BIAS_OFF + slot * BIAS_STG;
#pragma unroll
                for (int q = 0; q < 16; ++q) {
                    const int u = q * 128 + tid;
                    const int row = u >> 4, c4 = u & 15;
                    CP_ASYNC16(dbase + row * 256 + c4 * 16,
                               bias + (size_t)(ibase + row) * N_TOK + jb2 + c4 * 4);
                }
            }
            CP_COMMIT();

            /* generate P tile: 128 rows x 64 j -> f16 */
            char* ph = sm + PH_OFF + st * 18432;
            const char* bslot = sm + BIAS_OFF + (t & 3) * BIAS_STG;
            const float4 f2v = *((const float4*)(g_f2 + jb) + jq);
#pragma unroll 4
            for (int k = 0; k < 16; ++k) {
                const int i = rgrp + k * 8;
                const float f1v = f1s[i];
                const float mi  = ms[i];
                const float4 bv = *(const float4*)(bslot + i * 256 + jq * 16);
                float x, p0, p1, p2, p3;
                x = f1v + f2v.x; x = fmaxf(x, 0.2f * x) + bv.x - mi; p0 = __expf(x);
                x = f1v + f2v.y; x = fmaxf(x, 0.2f * x) + bv.y - mi; p1 = __expf(x);
                x = f1v + f2v.z; x = fmaxf(x, 0.2f * x) + bv.z - mi; p2 = __expf(x);
                x = f1v + f2v.w; x = fmaxf(x, 0.2f * x) + bv.w - mi; p3 = __expf(x);

                *(uint2*)(ph + i * PSTRB + jq * 8) =
                    make_uint2(cvt2h(p0, p1), cvt2h(p2, p3));

                float rs = (p0 + p1) + (p2 + p3);
                rs += __shfl_xor_sync(0xffffffffu, rs, 8);
                rs += __shfl_xor_sync(0xffffffffu, rs, 4);
                rs += __shfl_xor_sync(0xffffffffu, rs, 2);
                rs += __shfl_xor_sync(0xffffffffu, rs, 1);
                if (jq == 0) dens[i] += rs;
            }
            BAR_ARRIVE(1 + st);                      /* signal P full */
        }
    } else {
        /* ===================== CONSUMER ===================== */
        const int cw   = wid - 4;                    /* 0..3 */
        const int ctid = tid - 128;                  /* 0..127 */
        float acc[2][8][4];
#pragma unroll
        for (int b = 0; b < 2; ++b)
#pragma unroll
            for (int n = 0; n < 8; ++n)
#pragma unroll
                for (int q = 0; q < 4; ++q) acc[b][n][q] = 0.f;

        const uint32_t rsel = (uint32_t)(lane & 15) * PSTRB + (uint32_t)(lane >> 4) * 16;
        const uint32_t vhb = sbase + VH_OFF;

        for (int t = 0; t < NT_PER_CTA; ++t) {
            const int st = t & 1;
            const int jb = jbase0 + t * JT;

            /* issue V loads early (latency hides under the full-wait) */
            uint4 vh_r[4];
#pragma unroll
            for (int r = 0; r < 4; ++r) {
                const int u = r * 128 + ctid;
                const int c = u >> 3, q = u & 7;
                vh_r[r] = *((const uint4*)(g_ftsT + (size_t)c * N_TOK + jb) + q);
            }

            BAR_SYNC(1 + st);                        /* P full; all consumers past t-1 */

            /* stage V into (single) smem buffer */
#pragma unroll
            for (int r = 0; r < 4; ++r) {
                const int u = r * 128 + ctid;
                const int c = u >> 3, q = u & 7;
                *(uint4*)(sm + VH_OFF + c * PSTRB + q * 16) = vh_r[r];
            }
            BARH_SYNC(7);                            /* V visible to all consumers */

            const uint32_t ph = sbase + PH_OFF + st * 18432;

#pragma unroll
            for (int ks = 0; ks < 4; ++ks) {
                const uint32_t kofs = (uint32_t)ks * 32;   /* 16 f16 = 32B */
                uint32_t ah0[4], ah1[4];
                ldsm4(ah0[0], ah0[1], ah0[2], ah0[3],
                      ph + (cw * 32) * PSTRB + kofs + rsel);
                ldsm4(ah1[0], ah1[1], ah1[2], ah1[3],
                      ph + (cw * 32 + 16) * PSTRB + kofs + rsel);
#pragma unroll
                for (int np = 0; np < 4; ++np) {
                    uint32_t bh[4];
                    ldsm4(bh[0], bh[1], bh[2], bh[3],
                          vhb + (np * 16) * PSTRB + kofs + rsel);
                    mma16816(acc[0][np * 2],     ah0, bh[0], bh[2]);
                    mma16816(acc[0][np * 2 + 1], ah0, bh[1], bh[3]);
                    mma16816(acc[1][np * 2],     ah1, bh[0], bh[2]);
                    mma16816(acc[1][np * 2 + 1], ah1, bh[1], bh[3]);
                }
            }
            BAR_ARRIVE(3 + st);                      /* signal P empty */
        }

        /* write partials */
#pragma unroll
        for (int b = 0; b < 2; ++b) {
            const int m = cw * 32 + b * 16 + (lane >> 2);
            float* dst0 = g_acc + ((size_t)s * N_TOK + ibase + m) * OUTD;
            float* dst8 = dst0 + 8 * OUTD;
#pragma unroll
            for (int n = 0; n < 8; ++n) {
                const int c = n * 8 + (lane & 3) * 2;
                *(float2*)(dst0 + c) = make_float2(acc[b][n][0], acc[b][n][1]);
                *(float2*)(dst8 + c) = make_float2(acc[b][n][2], acc[b][n][3]);
            }
        }
    }

    __syncthreads();
    if (tid < M_TILE) g_den[s * N_TOK + ibase + tid] = dens[tid];
}

/* ------------------------------------------------------------------ */
__global__ __launch_bounds__(256) void k4_combine(float* __restrict__ out) {
    const int idx = blockIdx.x * 256 + threadIdx.x;
    if (idx >= N_TOK * 16) return;
    const int i = idx >> 4;
    float den = 0.f;
    float4 a = make_float4(0.f, 0.f, 0.f, 0.f);
#pragma unroll
    for (int s = 0; s < NSPLIT; ++s) {
        den += g_den[s * N_TOK + i];
        const float4 p = ((const float4*)g_acc)[(size_t)s * N_TOK * 16 + idx];
        a.x += p.x; a.y += p.y; a.z += p.z; a.w += p.w;
    }
    const float inv = 1.f / den;
    float4 r = make_float4(a.x * inv, a.y * inv, a.z * inv, a.w * inv);
    r.x = r.x > 0.f ? r.x : expm1f(r.x);
    r.y = r.y > 0.f ? r.y : expm1f(r.y);
    r.z = r.z > 0.f ? r.z : expm1f(r.z);
    r.w = r.w > 0.f ? r.w : expm1f(r.w);
    ((float4*)out)[idx] = r;
}

/* ------------------------------------------------------------------ */
extern "C" void kernel_launch(void* const* d_in, const int* in_sizes, int n_in,
                              void* d_out, int out_size) {
    const float* seq  = (const float*)d_in[0];
    const float* bias = (const float*)d_in[1];
    const float* W1   = (const float*)d_in[2];
    const float* a1   = (const float*)d_in[3];
    const float* b1   = (const float*)d_in[4];
    const float* a2   = (const float*)d_in[5];
    const float* b2   = (const float*)d_in[6];
    float* out = (float*)d_out;

    cudaFuncSetAttribute(k3_attn, cudaFuncAttributeMaxDynamicSharedMemorySize, SMEM3_BYTES);

    k1_fts<<<128, 256>>>(seq, W1, a1, b1, a2, b2);
    k2_max<<<1, 256>>>();
    dim3 g3(N_TOK / M_TILE, NSPLIT);
    k3_attn<<<g3, 256, SMEM3_BYTES>>>(bias);
    k4_combine<<<(N_TOK * 16) / 256, 256>>>(out);
}

// round 6
// speedup vs baseline: 4.4215x; 1.5025x over previous
#include <cuda_runtime.h>
#include <cuda_bf16.h>
#include <cuda_fp16.h>
#include <math.h>
#include <cstdint>

#define N_TOK 8192
#define F_DIM 256
#define OUTD  64
#define NSPLIT 2
#define JCHUNK (N_TOK / NSPLIT)   /* 4096 */
#define M_TILE 128
#define JT 64                     /* j per tile */
#define NT_PER_CTA (JCHUNK / JT)  /* 64 tiles */
#define LOG2E 1.4426950408889634f

/* ---------------- scratch (no allocation allowed) ---------------- */
__device__ __half g_ftsT[OUTD * N_TOK];            /* [c][j] transposed f16 */
__device__ float g_f1[N_TOK];
__device__ float g_f2[N_TOK];
__device__ float g_f2max;
__device__ float g_acc[NSPLIT * N_TOK * OUTD];     /* 4 MB */
__device__ float g_den[NSPLIT * N_TOK];

/* ---------------- helpers ---------------- */
__device__ __forceinline__ uint32_t smem_u32(const void* p) {
    uint32_t a;
    asm("{ .reg .u64 t; cvta.to.shared.u64 t, %1; cvt.u32.u64 %0, t; }" : "=r"(a) : "l"(p));
    return a;
}
/* pack two fp32 -> f16x2, memory order [a, b] */
__device__ __forceinline__ uint32_t cvt2h(float a, float b) {
    uint32_t r;
    asm("cvt.rn.f16x2.f32 %0, %1, %2;" : "=r"(r) : "f"(b), "f"(a));
    return r;
}
__device__ __forceinline__ uint32_t ex2h2(uint32_t x) {
    uint32_t r;
    asm("ex2.approx.f16x2 %0, %1;" : "=r"(r) : "r"(x));
    return r;
}
__device__ __forceinline__ void ldsm4(uint32_t& r0, uint32_t& r1, uint32_t& r2, uint32_t& r3,
                                      uint32_t addr) {
    asm volatile("ldmatrix.sync.aligned.m8n8.x4.shared.b16 {%0,%1,%2,%3}, [%4];"
                 : "=r"(r0), "=r"(r1), "=r"(r2), "=r"(r3) : "r"(addr));
}
__device__ __forceinline__ void mma16816(float* d, const uint32_t* a, uint32_t b0, uint32_t b1) {
    asm volatile("mma.sync.aligned.m16n8k16.row.col.f32.f16.f16.f32 "
                 "{%0,%1,%2,%3},{%4,%5,%6,%7},{%8,%9},{%0,%1,%2,%3};"
                 : "+f"(d[0]), "+f"(d[1]), "+f"(d[2]), "+f"(d[3])
                 : "r"(a[0]), "r"(a[1]), "r"(a[2]), "r"(a[3]), "r"(b0), "r"(b1));
}
#define BAR_SYNC(id)   asm volatile("bar.sync %0, 256;"   :: "r"(id) : "memory")
#define BAR_ARRIVE(id) asm volatile("bar.arrive %0, 256;" :: "r"(id) : "memory")
#define BARH_SYNC(id)  asm volatile("bar.sync %0, 128;"   :: "r"(id) : "memory")
#define CP_ASYNC16(dst, src) \
    asm volatile("cp.async.cg.shared.global [%0], [%1], 16;" :: "r"(dst), "l"(src) : "memory")
#define CP_COMMIT() asm volatile("cp.async.commit_group;" ::: "memory")
#define CP_WAIT2()  asm volatile("cp.async.wait_group 2;" ::: "memory")

/* ------------------------------------------------------------------ */
/* k1: seq_fts = seq @ W1 -> transposed f16 ; f1, f2                   */
/* ------------------------------------------------------------------ */
__global__ __launch_bounds__(256) void k1_fts(const float* __restrict__ seq,
        const float* __restrict__ W1, const float* __restrict__ a1,
        const float* __restrict__ b1, const float* __restrict__ a2,
        const float* __restrict__ b2) {
    __shared__ float As[64 * 68];
    __shared__ float Bs[64 * 64];
    __shared__ float a1s[OUTD], a2s[OUTD];

    const int tid = threadIdx.x;
    const int rb  = blockIdx.x * 64;
    if (tid < OUTD) { a1s[tid] = a1[tid]; a2s[tid] = a2[tid]; }

    const int cg = tid & 15, rg = tid >> 4;
    const int r0 = rg * 4,  c0 = cg * 4;

    float acc[4][4];
#pragma unroll
    for (int i = 0; i < 4; ++i)
#pragma unroll
        for (int j = 0; j < 4; ++j) acc[i][j] = 0.f;

    const float4* seq4 = (const float4*)seq;
    const float4* W14  = (const float4*)W1;
    float4* As4 = (float4*)As;
    float4* Bs4 = (float4*)Bs;

    for (int kb = 0; kb < 4; ++kb) {
        __syncthreads();
#pragma unroll
        for (int t = tid; t < 1024; t += 256) {
            const int r = t >> 4, c4 = t & 15;
            As4[r * 17 + c4] = seq4[(rb + r) * 64 + kb * 16 + c4];
            Bs4[t]           = W14[(kb * 64 + r) * 16 + c4];
        }
        __syncthreads();
#pragma unroll
        for (int k = 0; k < 64; ++k) {
            const float4 b = Bs4[k * 16 + cg];
#pragma unroll
            for (int ri = 0; ri < 4; ++ri) {
                const float a = As[(r0 + ri) * 68 + k];
                acc[ri][0] += a * b.x; acc[ri][1] += a * b.y;
                acc[ri][2] += a * b.z; acc[ri][3] += a * b.w;
            }
        }
    }

    /* write transposed f16: g_ftsT[c][row] */
#pragma unroll
    for (int ci = 0; ci < 4; ++ci) {
        const int c = c0 + ci;
        *(uint2*)(g_ftsT + (size_t)c * N_TOK + rb + r0) =
            make_uint2(cvt2h(acc[0][ci], acc[1][ci]), cvt2h(acc[2][ci], acc[3][ci]));
    }

    /* f1 / f2 */
#pragma unroll
    for (int ri = 0; ri < 4; ++ri) {
        float p1 = acc[ri][0] * a1s[c0] + acc[ri][1] * a1s[c0 + 1]
                 + acc[ri][2] * a1s[c0 + 2] + acc[ri][3] * a1s[c0 + 3];
        float p2 = acc[ri][0] * a2s[c0] + acc[ri][1] * a2s[c0 + 1]
                 + acc[ri][2] * a2s[c0 + 2] + acc[ri][3] * a2s[c0 + 3];
#pragma unroll
        for (int off = 8; off > 0; off >>= 1) {
            p1 += __shfl_xor_sync(0xffffffffu, p1, off);
            p2 += __shfl_xor_sync(0xffffffffu, p2, off);
        }
        if (cg == 0) {
            g_f1[rb + r0 + ri] = p1 + b1[0];
            g_f2[rb + r0 + ri] = p2 + b2[0];
        }
    }
}

/* ------------------------------------------------------------------ */
__global__ void k2_max() {
    __shared__ float red[256];
    const int tid = threadIdx.x;
    float m = -1e30f;
    for (int i = tid; i < N_TOK; i += 256) m = fmaxf(m, g_f2[i]);
    red[tid] = m; __syncthreads();
    for (int s = 128; s > 0; s >>= 1) {
        if (tid < s) red[tid] = fmaxf(red[tid], red[tid + s]);
        __syncthreads();
    }
    if (tid == 0) g_f2max = red[0];
}

/* ------------------------------------------------------------------ */
/* k3: warp-specialized P-gen (f16x2 ex2) + f16 mma.sync               */
/* warps 0-3: bias cp.async ring + P-gen; warps 4-7: V stage + HMMA    */
/* denominator computed by MMA against a ones-column block in V        */
/* ------------------------------------------------------------------ */
#define PSTRB 144                 /* bytes per smem tile row (72 f16) */
#define PH_OFF 0                  /* 2 stages x 128*144 = 36864 */
#define VH_OFF 36864              /* 80 rows x 144 = 11520 (64 V + 16 ones) */
#define FCL_OFF 48384             /* 128 x float2 = 1024 */
#define BIAS_OFF 49408            /* 4 stages x 32768 */
#define BIAS_STG 32768
#define SMEM3_BYTES (BIAS_OFF + 4 * BIAS_STG)   /* 180480 */

__global__ __launch_bounds__(256, 1) void k3_attn(const float* __restrict__ bias) {
    extern __shared__ char sm[];
    const uint32_t sbase = smem_u32(sm);
    float2* fcl = (float2*)(sm + FCL_OFF);        /* {f1, -m*log2e} per row */

    const int tid  = threadIdx.x;
    const int wid  = tid >> 5, lane = tid & 31;
    const int ibase = blockIdx.x * M_TILE;
    const int s     = blockIdx.y;
    const int jbase0 = s * JCHUNK;

    if (tid < M_TILE) {
        const float f1v = g_f1[ibase + tid];
        const float x = f1v + g_f2max;
        fcl[tid] = make_float2(f1v, -fmaxf(x, 0.2f * x) * LOG2E);
    }
    __syncthreads();

    if (wid < 4) {
        /* ===================== PRODUCER ===================== */
        const int jq    = lane & 15;
        const int rgrp  = wid * 2 + (lane >> 4);     /* 0..7 */

        /* prologue: prefetch bias tiles 0,1,2 */
#pragma unroll
        for (int pt = 0; pt < 3; ++pt) {
            const int jb2 = jbase0 + pt * JT;
            const uint32_t dbase = sbase + BIAS_OFF + pt * BIAS_STG;
#pragma unroll
            for (int q = 0; q < 16; ++q) {
                const int u = q * 128 + tid;
                const int row = u >> 4, c4 = u & 15;
                CP_ASYNC16(dbase + row * 256 + c4 * 16,
                           bias + (size_t)(ibase + row) * N_TOK + jb2 + c4 * 4);
            }
            CP_COMMIT();
        }

        for (int t = 0; t < NT_PER_CTA; ++t) {
            const int st = t & 1;
            const int jb = jbase0 + t * JT;
            if (t >= 2) BAR_SYNC(3 + st);            /* P buffer empty */

            CP_WAIT2();                               /* bias tile t landed (mine) */
            BARH_SYNC(5);                             /* all producers synced */

            /* prefetch bias tile t+3 */
            if (t + 3 < NT_PER_CTA) {
                const int slot = (t + 3) & 3;
                const int jb2 = jbase0 + (t + 3) * JT;
                const uint32_t dbase = sbase + BIAS_OFF + slot * BIAS_STG;
#pragma unroll
                for (int q = 0; q < 16; ++q) {
                    const int u = q * 128 + tid;
                    const int row = u >> 4, c4 = u & 15;
                    CP_ASYNC16(dbase + row * 256 + c4 * 16,
                               bias + (size_t)(ibase + row) * N_TOK + jb2 + c4 * 4);
                }
            }
            CP_COMMIT();

            /* generate P tile: 128 rows x 64 j -> f16 via ex2.f16x2 */
            char* ph = sm + PH_OFF + st * 18432;
            const char* bslot = sm + BIAS_OFF + (t & 3) * BIAS_STG;
            const float4 f2v = *((const float4*)(g_f2 + jb) + jq);
#pragma unroll 4
            for (int k = 0; k < 16; ++k) {
                const int i = rgrp + k * 8;
                const float2 fc = fcl[i];
                const float4 bv = *(const float4*)(bslot + i * 256 + jq * 16);
                float x, t0, t1, t2, t3;
                x = fc.x + f2v.x; t0 = fmaxf(x, 0.2f * x);
                x = fc.x + f2v.y; t1 = fmaxf(x, 0.2f * x);
                x = fc.x + f2v.z; t2 = fmaxf(x, 0.2f * x);
                x = fc.x + f2v.w; t3 = fmaxf(x, 0.2f * x);
                const float g0 = fmaf(t0, LOG2E, fmaf(bv.x, LOG2E, fc.y));
                const float g1 = fmaf(t1, LOG2E, fmaf(bv.y, LOG2E, fc.y));
                const float g2 = fmaf(t2, LOG2E, fmaf(bv.z, LOG2E, fc.y));
                const float g3 = fmaf(t3, LOG2E, fmaf(bv.w, LOG2E, fc.y));
                *(uint2*)(ph + i * PSTRB + jq * 8) =
                    make_uint2(ex2h2(cvt2h(g0, g1)), ex2h2(cvt2h(g2, g3)));
            }
            BAR_ARRIVE(1 + st);                      /* signal P full */
        }
    } else {
        /* ===================== CONSUMER ===================== */
        const int cw   = wid - 4;                    /* 0..3 */
        const int ctid = tid - 128;                  /* 0..127 */
        float acc[2][9][4];
#pragma unroll
        for (int b = 0; b < 2; ++b)
#pragma unroll
            for (int n = 0; n < 9; ++n)
#pragma unroll
                for (int q = 0; q < 4; ++q) acc[b][n][q] = 0.f;

        const uint32_t rsel = (uint32_t)(lane & 15) * PSTRB + (uint32_t)(lane >> 4) * 16;
        const uint32_t vhb = sbase + VH_OFF;

        /* init ones block: V rows 64..79 (col 64 = 1.0, cols 65..79 = 0) */
        for (int u = ctid; u < 16 * 36; u += 128) {
            const int r = u / 36, w = u % 36;
            ((uint32_t*)(sm + VH_OFF + (64 + r) * PSTRB))[w] = (r == 0) ? 0x3C003C00u : 0u;
        }

        for (int t = 0; t < NT_PER_CTA; ++t) {
            const int st = t & 1;
            const int jb = jbase0 + t * JT;

            /* issue V loads early (latency hides under the full-wait) */
            uint4 vh_r[4];
#pragma unroll
            for (int r = 0; r < 4; ++r) {
                const int u = r * 128 + ctid;
                const int c = u >> 3, q = u & 7;
                vh_r[r] = *((const uint4*)(g_ftsT + (size_t)c * N_TOK + jb) + q);
            }

            BAR_SYNC(1 + st);                        /* P full */

            /* stage V into (single) smem buffer */
#pragma unroll
            for (int r = 0; r < 4; ++r) {
                const int u = r * 128 + ctid;
                const int c = u >> 3, q = u & 7;
                *(uint4*)(sm + VH_OFF + c * PSTRB + q * 16) = vh_r[r];
            }
            BARH_SYNC(7);                            /* V (+ones) visible */

            const uint32_t ph = sbase + PH_OFF + st * 18432;

#pragma unroll
            for (int ks = 0; ks < 4; ++ks) {
                const uint32_t kofs = (uint32_t)ks * 32;   /* 16 f16 = 32B */
                uint32_t ah0[4], ah1[4];
                ldsm4(ah0[0], ah0[1], ah0[2], ah0[3],
                      ph + (cw * 32) * PSTRB + kofs + rsel);
                ldsm4(ah1[0], ah1[1], ah1[2], ah1[3],
                      ph + (cw * 32 + 16) * PSTRB + kofs + rsel);
#pragma unroll
                for (int np = 0; np < 4; ++np) {
                    uint32_t bh[4];
                    ldsm4(bh[0], bh[1], bh[2], bh[3],
                          vhb + (np * 16) * PSTRB + kofs + rsel);
                    mma16816(acc[0][np * 2],     ah0, bh[0], bh[2]);
                    mma16816(acc[0][np * 2 + 1], ah0, bh[1], bh[3]);
                    mma16816(acc[1][np * 2],     ah1, bh[0], bh[2]);
                    mma16816(acc[1][np * 2 + 1], ah1, bh[1], bh[3]);
                }
                /* ones block (rows 64..79): row-sum column */
                {
                    uint32_t bh[4];
                    ldsm4(bh[0], bh[1], bh[2], bh[3],
                          vhb + 64 * PSTRB + kofs + rsel);
                    mma16816(acc[0][8], ah0, bh[0], bh[2]);
                    mma16816(acc[1][8], ah1, bh[0], bh[2]);
                }
            }
            BAR_ARRIVE(3 + st);                      /* signal P empty */
        }

        /* write partials + denominators */
#pragma unroll
        for (int b = 0; b < 2; ++b) {
            const int m = cw * 32 + b * 16 + (lane >> 2);
            float* dst0 = g_acc + ((size_t)s * N_TOK + ibase + m) * OUTD;
            float* dst8 = dst0 + 8 * OUTD;
#pragma unroll
            for (int n = 0; n < 8; ++n) {
                const int c = n * 8 + (lane & 3) * 2;
                *(float2*)(dst0 + c) = make_float2(acc[b][n][0], acc[b][n][1]);
                *(float2*)(dst8 + c) = make_float2(acc[b][n][2], acc[b][n][3]);
            }
            if ((lane & 3) == 0) {
                g_den[(size_t)s * N_TOK + ibase + m]     = acc[b][8][0];
                g_den[(size_t)s * N_TOK + ibase + m + 8] = acc[b][8][2];
            }
        }
    }
}

/* ------------------------------------------------------------------ */
__global__ __launch_bounds__(256) void k4_combine(float* __restrict__ out) {
    const int idx = blockIdx.x * 256 + threadIdx.x;
    if (idx >= N_TOK * 16) return;
    const int i = idx >> 4;
    float den = 0.f;
    float4 a = make_float4(0.f, 0.f, 0.f, 0.f);
#pragma unroll
    for (int s = 0; s < NSPLIT; ++s) {
        den += g_den[s * N_TOK + i];
        const float4 p = ((const float4*)g_acc)[(size_t)s * N_TOK * 16 + idx];
        a.x += p.x; a.y += p.y; a.z += p.z; a.w += p.w;
    }
    const float inv = 1.f / den;
    float4 r = make_float4(a.x * inv, a.y * inv, a.z * inv, a.w * inv);
    r.x = r.x > 0.f ? r.x : expm1f(r.x);
    r.y = r.y > 0.f ? r.y : expm1f(r.y);
    r.z = r.z > 0.f ? r.z : expm1f(r.z);
    r.w = r.w > 0.f ? r.w : expm1f(r.w);
    ((float4*)out)[idx] = r;
}

/* ------------------------------------------------------------------ */
extern "C" void kernel_launch(void* const* d_in, const int* in_sizes, int n_in,
                              void* d_out, int out_size) {
    const float* seq  = (const float*)d_in[0];
    const float* bias = (const float*)d_in[1];
    const float* W1   = (const float*)d_in[2];
    const float* a1   = (const float*)d_in[3];
    const float* b1   = (const float*)d_in[4];
    const float* a2   = (const float*)d_in[5];
    const float* b2   = (const float*)d_in[6];
    float* out = (float*)d_out;

    cudaFuncSetAttribute(k3_attn, cudaFuncAttributeMaxDynamicSharedMemorySize, SMEM3_BYTES);

    k1_fts<<<128, 256>>>(seq, W1, a1, b1, a2, b2);
    k2_max<<<1, 256>>>();
    dim3 g3(N_TOK / M_TILE, NSPLIT);
    k3_attn<<<g3, 256, SMEM3_BYTES>>>(bias);
    k4_combine<<<(N_TOK * 16) / 256, 256>>>(out);
}

// round 7
// speedup vs baseline: 5.9744x; 1.3512x over previous
#include <cuda_runtime.h>
#include <cuda_bf16.h>
#include <cuda_fp16.h>
#include <math.h>
#include <cstdint>

#define N_TOK 8192
#define F_DIM 256
#define OUTD  64
#define NSPLIT 2
#define JCHUNK (N_TOK / NSPLIT)   /* 4096 */
#define M_TILE 128
#define JT 64                     /* j per tile */
#define NT_PER_CTA (JCHUNK / JT)  /* 64 tiles */
#define LOG2E 1.4426950408889634f

/* ---------------- scratch (no allocation allowed) ---------------- */
__device__ __half g_ftsT[OUTD * N_TOK];            /* [c][j] transposed f16 */
__device__ float g_f1[N_TOK];
__device__ float g_f2[N_TOK];
__device__ float g_f2max;
__device__ float g_acc[NSPLIT * N_TOK * OUTD];     /* 4 MB */
__device__ float g_den[NSPLIT * N_TOK];

/* ---------------- helpers ---------------- */
__device__ __forceinline__ uint32_t smem_u32(const void* p) {
    uint32_t a;
    asm("{ .reg .u64 t; cvta.to.shared.u64 t, %1; cvt.u32.u64 %0, t; }" : "=r"(a) : "l"(p));
    return a;
}
/* pack two fp32 -> f16x2, memory order [a, b] */
__device__ __forceinline__ uint32_t cvt2h(float a, float b) {
    uint32_t r;
    asm("cvt.rn.f16x2.f32 %0, %1, %2;" : "=r"(r) : "f"(b), "f"(a));
    return r;
}
__device__ __forceinline__ uint32_t ex2h2(uint32_t x) {
    uint32_t r;
    asm("ex2.approx.f16x2 %0, %1;" : "=r"(r) : "r"(x));
    return r;
}
__device__ __forceinline__ void ldsm4(uint32_t& r0, uint32_t& r1, uint32_t& r2, uint32_t& r3,
                                      uint32_t addr) {
    asm volatile("ldmatrix.sync.aligned.m8n8.x4.shared.b16 {%0,%1,%2,%3}, [%4];"
                 : "=r"(r0), "=r"(r1), "=r"(r2), "=r"(r3) : "r"(addr));
}
__device__ __forceinline__ void mma16816(float* d, const uint32_t* a, uint32_t b0, uint32_t b1) {
    asm volatile("mma.sync.aligned.m16n8k16.row.col.f32.f16.f16.f32 "
                 "{%0,%1,%2,%3},{%4,%5,%6,%7},{%8,%9},{%0,%1,%2,%3};"
                 : "+f"(d[0]), "+f"(d[1]), "+f"(d[2]), "+f"(d[3])
                 : "r"(a[0]), "r"(a[1]), "r"(a[2]), "r"(a[3]), "r"(b0), "r"(b1));
}
/* full/empty barriers span producers+consumers = 512 threads */
#define BAR_SYNC512(id)   asm volatile("bar.sync %0, 512;"   :: "r"(id) : "memory")
#define BAR_ARRIVE512(id) asm volatile("bar.arrive %0, 512;" :: "r"(id) : "memory")
/* intra-role barriers: 256 threads */
#define BAR_SYNC256(id)   asm volatile("bar.sync %0, 256;"   :: "r"(id) : "memory")
#define CP_ASYNC16(dst, src) \
    asm volatile("cp.async.cg.shared.global [%0], [%1], 16;" :: "r"(dst), "l"(src) : "memory")
#define CP_COMMIT() asm volatile("cp.async.commit_group;" ::: "memory")
#define CP_WAIT2()  asm volatile("cp.async.wait_group 2;" ::: "memory")

/* ------------------------------------------------------------------ */
/* k1: seq_fts = seq @ W1 -> transposed f16 ; f1, f2                   */
/* ------------------------------------------------------------------ */
__global__ __launch_bounds__(256) void k1_fts(const float* __restrict__ seq,
        const float* __restrict__ W1, const float* __restrict__ a1,
        const float* __restrict__ b1, const float* __restrict__ a2,
        const float* __restrict__ b2) {
    __shared__ float As[64 * 68];
    __shared__ float Bs[64 * 64];
    __shared__ float a1s[OUTD], a2s[OUTD];

    const int tid = threadIdx.x;
    const int rb  = blockIdx.x * 64;
    if (tid < OUTD) { a1s[tid] = a1[tid]; a2s[tid] = a2[tid]; }

    const int cg = tid & 15, rg = tid >> 4;
    const int r0 = rg * 4,  c0 = cg * 4;

    float acc[4][4];
#pragma unroll
    for (int i = 0; i < 4; ++i)
#pragma unroll
        for (int j = 0; j < 4; ++j) acc[i][j] = 0.f;

    const float4* seq4 = (const float4*)seq;
    const float4* W14  = (const float4*)W1;
    float4* As4 = (float4*)As;
    float4* Bs4 = (float4*)Bs;

    for (int kb = 0; kb < 4; ++kb) {
        __syncthreads();
#pragma unroll
        for (int t = tid; t < 1024; t += 256) {
            const int r = t >> 4, c4 = t & 15;
            As4[r * 17 + c4] = seq4[(rb + r) * 64 + kb * 16 + c4];
            Bs4[t]           = W14[(kb * 64 + r) * 16 + c4];
        }
        __syncthreads();
#pragma unroll
        for (int k = 0; k < 64; ++k) {
            const float4 b = Bs4[k * 16 + cg];
#pragma unroll
            for (int ri = 0; ri < 4; ++ri) {
                const float a = As[(r0 + ri) * 68 + k];
                acc[ri][0] += a * b.x; acc[ri][1] += a * b.y;
                acc[ri][2] += a * b.z; acc[ri][3] += a * b.w;
            }
        }
    }

    /* write transposed f16: g_ftsT[c][row] */
#pragma unroll
    for (int ci = 0; ci < 4; ++ci) {
        const int c = c0 + ci;
        *(uint2*)(g_ftsT + (size_t)c * N_TOK + rb + r0) =
            make_uint2(cvt2h(acc[0][ci], acc[1][ci]), cvt2h(acc[2][ci], acc[3][ci]));
    }

    /* f1 / f2 */
#pragma unroll
    for (int ri = 0; ri < 4; ++ri) {
        float p1 = acc[ri][0] * a1s[c0] + acc[ri][1] * a1s[c0 + 1]
                 + acc[ri][2] * a1s[c0 + 2] + acc[ri][3] * a1s[c0 + 3];
        float p2 = acc[ri][0] * a2s[c0] + acc[ri][1] * a2s[c0 + 1]
                 + acc[ri][2] * a2s[c0 + 2] + acc[ri][3] * a2s[c0 + 3];
#pragma unroll
        for (int off = 8; off > 0; off >>= 1) {
            p1 += __shfl_xor_sync(0xffffffffu, p1, off);
            p2 += __shfl_xor_sync(0xffffffffu, p2, off);
        }
        if (cg == 0) {
            g_f1[rb + r0 + ri] = p1 + b1[0];
            g_f2[rb + r0 + ri] = p2 + b2[0];
        }
    }
}

/* ------------------------------------------------------------------ */
__global__ void k2_max() {
    __shared__ float red[256];
    const int tid = threadIdx.x;
    float m = -1e30f;
    for (int i = tid; i < N_TOK; i += 256) m = fmaxf(m, g_f2[i]);
    red[tid] = m; __syncthreads();
    for (int s = 128; s > 0; s >>= 1) {
        if (tid < s) red[tid] = fmaxf(red[tid], red[tid + s]);
        __syncthreads();
    }
    if (tid == 0) g_f2max = red[0];
}

/* ------------------------------------------------------------------ */
/* k3: 512 threads: warps 0-7 produce P (bias ring + ex2.f16x2),       */
/* warps 8-15 consume (ldmatrix + f16 HMMA). Denominator via ones-col. */
/* ------------------------------------------------------------------ */
#define PSTRB 144                 /* bytes per smem tile row (72 f16) */
#define PH_OFF 0                  /* 2 stages x 128*144 = 36864 */
#define VH_OFF 36864              /* 80 rows x 144 = 11520 (64 V + 16 ones) */
#define FCL_OFF 48384             /* 128 x float2 = 1024 */
#define BIAS_OFF 49408            /* 4 stages x 32768 */
#define BIAS_STG 32768
#define SMEM3_BYTES (BIAS_OFF + 4 * BIAS_STG)   /* 180480 */

__global__ __launch_bounds__(512, 1) void k3_attn(const float* __restrict__ bias) {
    extern __shared__ char sm[];
    const uint32_t sbase = smem_u32(sm);
    float2* fcl = (float2*)(sm + FCL_OFF);        /* {f1, -m*log2e} per row */

    const int tid  = threadIdx.x;
    const int wid  = tid >> 5, lane = tid & 31;
    const int ibase = blockIdx.x * M_TILE;
    const int s     = blockIdx.y;
    const int jbase0 = s * JCHUNK;

    if (tid < M_TILE) {
        const float f1v = g_f1[ibase + tid];
        const float x = f1v + g_f2max;
        fcl[tid] = make_float2(f1v, -fmaxf(x, 0.2f * x) * LOG2E);
    }
    __syncthreads();

    if (wid < 8) {
        /* ===================== PRODUCERS (256 thr) ===================== */
        const int jq    = lane & 15;
        const int rgrp  = wid * 2 + (lane >> 4);     /* 0..15 */

        /* prologue: prefetch bias tiles 0,1,2 */
#pragma unroll
        for (int pt = 0; pt < 3; ++pt) {
            const int jb2 = jbase0 + pt * JT;
            const uint32_t dbase = sbase + BIAS_OFF + pt * BIAS_STG;
#pragma unroll
            for (int q = 0; q < 8; ++q) {
                const int u = q * 256 + tid;
                const int row = u >> 4, c4 = u & 15;
                CP_ASYNC16(dbase + row * 256 + c4 * 16,
                           bias + (size_t)(ibase + row) * N_TOK + jb2 + c4 * 4);
            }
            CP_COMMIT();
        }

        for (int t = 0; t < NT_PER_CTA; ++t) {
            const int st = t & 1;
            const int jb = jbase0 + t * JT;
            if (t >= 2) BAR_SYNC512(3 + st);         /* P buffer empty */

            CP_WAIT2();                               /* bias tile t landed (mine) */
            BAR_SYNC256(5);                           /* all producers synced */

            /* prefetch bias tile t+3 */
            if (t + 3 < NT_PER_CTA) {
                const int slot = (t + 3) & 3;
                const int jb2 = jbase0 + (t + 3) * JT;
                const uint32_t dbase = sbase + BIAS_OFF + slot * BIAS_STG;
#pragma unroll
                for (int q = 0; q < 8; ++q) {
                    const int u = q * 256 + tid;
                    const int row = u >> 4, c4 = u & 15;
                    CP_ASYNC16(dbase + row * 256 + c4 * 16,
                               bias + (size_t)(ibase + row) * N_TOK + jb2 + c4 * 4);
                }
            }
            CP_COMMIT();

            /* generate P tile: 128 rows x 64 j -> f16 via ex2.f16x2 */
            char* ph = sm + PH_OFF + st * 18432;
            const char* bslot = sm + BIAS_OFF + (t & 3) * BIAS_STG;
            const float4 f2v = *((const float4*)(g_f2 + jb) + jq);
#pragma unroll
            for (int k = 0; k < 8; ++k) {
                const int i = rgrp + k * 16;
                const float2 fc = fcl[i];
                const float4 bv = *(const float4*)(bslot + i * 256 + jq * 16);
                float x, t0, t1, t2, t3;
                x = fc.x + f2v.x; t0 = fmaxf(x, 0.2f * x);
                x = fc.x + f2v.y; t1 = fmaxf(x, 0.2f * x);
                x = fc.x + f2v.z; t2 = fmaxf(x, 0.2f * x);
                x = fc.x + f2v.w; t3 = fmaxf(x, 0.2f * x);
                const float g0 = fmaf(t0, LOG2E, fmaf(bv.x, LOG2E, fc.y));
                const float g1 = fmaf(t1, LOG2E, fmaf(bv.y, LOG2E, fc.y));
                const float g2 = fmaf(t2, LOG2E, fmaf(bv.z, LOG2E, fc.y));
                const float g3 = fmaf(t3, LOG2E, fmaf(bv.w, LOG2E, fc.y));
                *(uint2*)(ph + i * PSTRB + jq * 8) =
                    make_uint2(ex2h2(cvt2h(g0, g1)), ex2h2(cvt2h(g2, g3)));
            }
            BAR_ARRIVE512(1 + st);                   /* signal P full */
        }
    } else {
        /* ===================== CONSUMERS (256 thr) ===================== */
        const int cw   = wid - 8;                    /* 0..7, 16 rows each */
        const int ctid = tid - 256;                  /* 0..255 */
        float acc[9][4];
#pragma unroll
        for (int n = 0; n < 9; ++n)
#pragma unroll
            for (int q = 0; q < 4; ++q) acc[n][q] = 0.f;

        const uint32_t rsel = (uint32_t)(lane & 15) * PSTRB + (uint32_t)(lane >> 4) * 16;
        const uint32_t vhb = sbase + VH_OFF;

        /* init ones block: V rows 64..79 (col 64 = 1.0, cols 65..79 = 0) */
        for (int u = ctid; u < 16 * 36; u += 256) {
            const int r = u / 36, w = u % 36;
            ((uint32_t*)(sm + VH_OFF + (64 + r) * PSTRB))[w] = (r == 0) ? 0x3C003C00u : 0u;
        }

        for (int t = 0; t < NT_PER_CTA; ++t) {
            const int st = t & 1;
            const int jb = jbase0 + t * JT;

            /* issue V loads early (latency hides under the full-wait) */
            uint4 vh_r[2];
#pragma unroll
            for (int r = 0; r < 2; ++r) {
                const int u = r * 256 + ctid;
                const int c = u >> 3, q = u & 7;
                vh_r[r] = *((const uint4*)(g_ftsT + (size_t)c * N_TOK + jb) + q);
            }

            BAR_SYNC512(1 + st);                     /* P full */

            /* stage V into (single) smem buffer */
#pragma unroll
            for (int r = 0; r < 2; ++r) {
                const int u = r * 256 + ctid;
                const int c = u >> 3, q = u & 7;
                *(uint4*)(sm + VH_OFF + c * PSTRB + q * 16) = vh_r[r];
            }
            BAR_SYNC256(7);                          /* V (+ones) visible */

            const uint32_t ph = sbase + PH_OFF + st * 18432;

#pragma unroll
            for (int ks = 0; ks < 4; ++ks) {
                const uint32_t kofs = (uint32_t)ks * 32;   /* 16 f16 = 32B */
                uint32_t ah[4];
                ldsm4(ah[0], ah[1], ah[2], ah[3],
                      ph + (cw * 16) * PSTRB + kofs + rsel);
#pragma unroll
                for (int np = 0; np < 4; ++np) {
                    uint32_t bh[4];
                    ldsm4(bh[0], bh[1], bh[2], bh[3],
                          vhb + (np * 16) * PSTRB + kofs + rsel);
                    mma16816(acc[np * 2],     ah, bh[0], bh[2]);
                    mma16816(acc[np * 2 + 1], ah, bh[1], bh[3]);
                }
                /* ones block (rows 64..79): row-sum column */
                {
                    uint32_t bh[4];
                    ldsm4(bh[0], bh[1], bh[2], bh[3],
                          vhb + 64 * PSTRB + kofs + rsel);
                    mma16816(acc[8], ah, bh[0], bh[2]);
                }
            }
            BAR_ARRIVE512(3 + st);                   /* signal P empty */
        }

        /* write partials + denominators (rows cw*16 .. cw*16+15) */
        {
            const int m = cw * 16 + (lane >> 2);
            float* dst0 = g_acc + ((size_t)s * N_TOK + ibase + m) * OUTD;
            float* dst8 = dst0 + 8 * OUTD;
#pragma unroll
            for (int n = 0; n < 8; ++n) {
                const int c = n * 8 + (lane & 3) * 2;
                *(float2*)(dst0 + c) = make_float2(acc[n][0], acc[n][1]);
                *(float2*)(dst8 + c) = make_float2(acc[n][2], acc[n][3]);
            }
            if ((lane & 3) == 0) {
                g_den[(size_t)s * N_TOK + ibase + m]     = acc[8][0];
                g_den[(size_t)s * N_TOK + ibase + m + 8] = acc[8][2];
            }
        }
    }
}

/* ------------------------------------------------------------------ */
__global__ __launch_bounds__(256) void k4_combine(float* __restrict__ out) {
    const int idx = blockIdx.x * 256 + threadIdx.x;
    if (idx >= N_TOK * 16) return;
    const int i = idx >> 4;
    float den = 0.f;
    float4 a = make_float4(0.f, 0.f, 0.f, 0.f);
#pragma unroll
    for (int s = 0; s < NSPLIT; ++s) {
        den += g_den[s * N_TOK + i];
        const float4 p = ((const float4*)g_acc)[(size_t)s * N_TOK * 16 + idx];
        a.x += p.x; a.y += p.y; a.z += p.z; a.w += p.w;
    }
    const float inv = 1.f / den;
    float4 r = make_float4(a.x * inv, a.y * inv, a.z * inv, a.w * inv);
    r.x = r.x > 0.f ? r.x : expm1f(r.x);
    r.y = r.y > 0.f ? r.y : expm1f(r.y);
    r.z = r.z > 0.f ? r.z : expm1f(r.z);
    r.w = r.w > 0.f ? r.w : expm1f(r.w);
    ((float4*)out)[idx] = r;
}

/* ------------------------------------------------------------------ */
extern "C" void kernel_launch(void* const* d_in, const int* in_sizes, int n_in,
                              void* d_out, int out_size) {
    const float* seq  = (const float*)d_in[0];
    const float* bias = (const float*)d_in[1];
    const float* W1   = (const float*)d_in[2];
    const float* a1   = (const float*)d_in[3];
    const float* b1   = (const float*)d_in[4];
    const float* a2   = (const float*)d_in[5];
    const float* b2   = (const float*)d_in[6];
    float* out = (float*)d_out;

    cudaFuncSetAttribute(k3_attn, cudaFuncAttributeMaxDynamicSharedMemorySize, SMEM3_BYTES);

    k1_fts<<<128, 256>>>(seq, W1, a1, b1, a2, b2);
    k2_max<<<1, 256>>>();
    dim3 g3(N_TOK / M_TILE, NSPLIT);
    k3_attn<<<g3, 512, SMEM3_BYTES>>>(bias);
    k4_combine<<<(N_TOK * 16) / 256, 256>>>(out);
}